// round 14
// baseline (speedup 1.0000x reference)
#include <cuda_runtime.h>
#include <cuda_bf16.h>
#include <cuda_fp8.h>
#include <cstdint>

#define B_  8
#define N_  2048
#define C_  512
#define CR_ 64

// Device-global scratch (no allocs allowed).
__device__ __nv_bfloat16 g_xb[(size_t)B_ * N_ * C_];    // x in bf16
__device__ __nv_bfloat16 g_Wb[(size_t)640 * C_];        // [Wk;Wv;Wq] bf16
__device__ __nv_bfloat16 g_K [(size_t)B_ * N_ * CR_];   // [b*N+n][64]
__device__ __nv_bfloat16 g_V [(size_t)B_ * N_ * CR_];   // [b*N+m][64]
__device__ unsigned char g_Q8[(size_t)B_ * C_ * N_];    // Qt e4m3: [b*C+c][n]
__device__ unsigned char g_P8[(size_t)B_ * N_ * N_];    // P^T e4m3: [b][m][n]
__device__ float         g_denp[(size_t)B_ * 4 * N_];   // partial den

__device__ __forceinline__ uint32_t smem_u32(const void* p) {
    uint32_t a;
    asm("{ .reg .u64 t; cvta.to.shared.u64 t, %1; cvt.u32.u64 %0, t; }" : "=r"(a) : "l"(p));
    return a;
}
__device__ __forceinline__ void cp16(uint32_t dst, const void* src) {
    asm volatile("cp.async.cg.shared.global [%0], [%1], 16;" :: "r"(dst), "l"(src));
}
#define CP_COMMIT() asm volatile("cp.async.commit_group;" ::: "memory")
#define CP_WAIT0()  asm volatile("cp.async.wait_group 0;"  ::: "memory")
#define CP_WAIT1()  asm volatile("cp.async.wait_group 1;"  ::: "memory")

__device__ __forceinline__ unsigned char f2e4m3(float f) {
    return (unsigned char)__nv_cvt_float_to_fp8(f, __NV_SATFINITE, __NV_E4M3);
}

// bf16 warp mma: D(16x8) += A(16x16)*B(16x8)
__device__ __forceinline__ void mma16(float d[4], const uint32_t a[4], uint32_t b0, uint32_t b1) {
    asm volatile(
        "mma.sync.aligned.m16n8k16.row.col.f32.bf16.bf16.f32 "
        "{%0,%1,%2,%3}, {%4,%5,%6,%7}, {%8,%9}, {%0,%1,%2,%3};"
        : "+f"(d[0]), "+f"(d[1]), "+f"(d[2]), "+f"(d[3])
        : "r"(a[0]), "r"(a[1]), "r"(a[2]), "r"(a[3]), "r"(b0), "r"(b1));
}
// fp8 warp mma: D(16x8) += A(16x32)*B(32x8), e4m3
__device__ __forceinline__ void mma32(float d[4], const uint32_t a[4], uint32_t b0, uint32_t b1) {
    asm volatile(
        "mma.sync.aligned.m16n8k32.row.col.f32.e4m3.e4m3.f32 "
        "{%0,%1,%2,%3}, {%4,%5,%6,%7}, {%8,%9}, {%0,%1,%2,%3};"
        : "+f"(d[0]), "+f"(d[1]), "+f"(d[2]), "+f"(d[3])
        : "r"(a[0]), "r"(a[1]), "r"(a[2]), "r"(a[3]), "r"(b0), "r"(b1));
}
__device__ __forceinline__ void ldm4(uint32_t r[4], uint32_t addr) {
    asm volatile("ldmatrix.sync.aligned.m8n8.x4.shared.b16 {%0,%1,%2,%3}, [%4];"
        : "=r"(r[0]), "=r"(r[1]), "=r"(r[2]), "=r"(r[3]) : "r"(addr));
}

// =======================================================================
// Kernel 0: fp32 -> bf16 conversion of x and [Wk;Wv;Wq].
// =======================================================================
__global__ __launch_bounds__(256) void cvt_kernel(
    const float* __restrict__ x,
    const float* __restrict__ Wk, const float* __restrict__ Wv,
    const float* __restrict__ Wq)
{
    const int NX = (B_ * N_ * C_) / 4;
    const int NW = (640 * C_) / 4;
    for (int i = blockIdx.x * blockDim.x + threadIdx.x; i < NX + NW;
         i += gridDim.x * blockDim.x) {
        float4 v;
        __nv_bfloat16* dst;
        if (i < NX) {
            v = ((const float4*)x)[i];
            dst = &g_xb[(size_t)i * 4];
        } else {
            int j = i - NX;
            const int row = (j * 4) / C_;
            const float* src;
            if (row < 64)        src = Wk;
            else if (row < 128)  src = Wv - 64 * C_;
            else                 src = Wq - 128 * C_;
            v = ((const float4*)src)[j];
            dst = &g_Wb[(size_t)j * 4];
        }
        __nv_bfloat162 p0 = __floats2bfloat162_rn(v.x, v.y);
        __nv_bfloat162 p1 = __floats2bfloat162_rn(v.z, v.w);
        ((__nv_bfloat162*)dst)[0] = p0;
        ((__nv_bfloat162*)dst)[1] = p1;
    }
}

// =======================================================================
// Kernel 1: projection GEMM (bf16 HMMA + ldmatrix), 128x128 tiles,
// ring-3, 1 barrier/iter. grid (5 o-tiles of 128, 128 row-tiles of 128).
// ot 0 -> K(64)+V(64); ot 1..4 -> Qt e4m3 (transposed), 128 chans each.
// =======================================================================
#define PITCH 72
#define PAB (128 * PITCH * 2)   // 18432 B per 128-row tile
#define PJ_A 0
#define PJ_B (PJ_A + 3 * PAB)
#define PJ_SMEM_BYTES (PJ_B + 3 * PAB)   // 110592
__global__ __launch_bounds__(256, 2) void proj_hmma(
    const float* __restrict__ bk, const float* __restrict__ bv,
    const float* __restrict__ bq)
{
    extern __shared__ char smc[];
    float* sT = (float*)smc;   // staging [128 oc][132 r] floats

    const uint32_t smu = smem_u32(smc);
    const uint32_t sAu = smu + PJ_A, sBu = smu + PJ_B;

    const int tid = threadIdx.x;
    const int wid = tid >> 5, lane = tid & 31;
    const int g = lane >> 2, t = lane & 3;
    const int wlo = wid & 3;        // row group (32 of 128)
    const int whi = wid >> 2;       // o group (64 of 128)
    const int lrow = lane & 15;
    const int lcol = (lane >> 4) << 3;

    const int ot = blockIdx.x;      // 0..4
    const int row0 = blockIdx.y * 128;
    const int wrow0 = ot * 128;

    #pragma unroll
    for (int pf = 0; pf < 2; pf++) {
        const int kc = pf * 64;
        const uint32_t ab = sAu + pf * PAB, bb = sBu + pf * PAB;
        #pragma unroll
        for (int l = 0; l < 4; l++) {
            int idx = tid + l * 256;
            int r = idx >> 3, ch = idx & 7;
            cp16(ab + r * 144 + ch * 16, &g_xb[(size_t)(row0 + r) * C_ + kc + ch * 8]);
            cp16(bb + r * 144 + ch * 16, &g_Wb[(size_t)(wrow0 + r) * C_ + kc + ch * 8]);
        }
        CP_COMMIT();
    }

    float acc[16][4];
    #pragma unroll
    for (int i = 0; i < 16; i++)
        #pragma unroll
        for (int j = 0; j < 4; j++) acc[i][j] = 0.f;

    const uint32_t aoff0 = ((32 * wlo + lrow) * PITCH + lcol) * 2;
    const uint32_t aoff1 = aoff0 + 16 * PITCH * 2;
    const uint32_t boff0 = ((64 * whi + lrow) * PITCH + lcol) * 2;
    const uint32_t boff1 = boff0 + 16 * PITCH * 2;
    const uint32_t boff2 = boff0 + 32 * PITCH * 2;
    const uint32_t boff3 = boff0 + 48 * PITCH * 2;

    uint32_t sl0 = 0, sl1 = 1, sl2 = 2;
    for (int it = 0; it < 8; it++) {
        CP_WAIT1();
        __syncthreads();

        if (it + 2 < 8) {
            const int kc = (it + 2) * 64;
            const uint32_t ab = sAu + sl2 * PAB, bb = sBu + sl2 * PAB;
            #pragma unroll
            for (int l = 0; l < 4; l++) {
                int idx = tid + l * 256;
                int r = idx >> 3, ch = idx & 7;
                cp16(ab + r * 144 + ch * 16, &g_xb[(size_t)(row0 + r) * C_ + kc + ch * 8]);
                cp16(bb + r * 144 + ch * 16, &g_Wb[(size_t)(wrow0 + r) * C_ + kc + ch * 8]);
            }
        }
        CP_COMMIT();

        const uint32_t Ab = sAu + sl0 * PAB;
        const uint32_t Bb = sBu + sl0 * PAB;

        #pragma unroll
        for (int kk = 0; kk < 64; kk += 16) {
            uint32_t a0[4], a1[4], b0[4], b1[4], b2[4], b3[4];
            ldm4(a0, Ab + aoff0 + kk * 2);
            ldm4(a1, Ab + aoff1 + kk * 2);
            ldm4(b0, Bb + boff0 + kk * 2);
            ldm4(b1, Bb + boff1 + kk * 2);
            ldm4(b2, Bb + boff2 + kk * 2);
            ldm4(b3, Bb + boff3 + kk * 2);
            mma16(acc[0],  a0, b0[0], b0[2]);
            mma16(acc[1],  a0, b0[1], b0[3]);
            mma16(acc[2],  a0, b1[0], b1[2]);
            mma16(acc[3],  a0, b1[1], b1[3]);
            mma16(acc[4],  a0, b2[0], b2[2]);
            mma16(acc[5],  a0, b2[1], b2[3]);
            mma16(acc[6],  a0, b3[0], b3[2]);
            mma16(acc[7],  a0, b3[1], b3[3]);
            mma16(acc[8],  a1, b0[0], b0[2]);
            mma16(acc[9],  a1, b0[1], b0[3]);
            mma16(acc[10], a1, b1[0], b1[2]);
            mma16(acc[11], a1, b1[1], b1[3]);
            mma16(acc[12], a1, b2[0], b2[2]);
            mma16(acc[13], a1, b2[1], b2[3]);
            mma16(acc[14], a1, b3[0], b3[2]);
            mma16(acc[15], a1, b3[1], b3[3]);
        }

        uint32_t tmp = sl0; sl0 = sl1; sl1 = sl2; sl2 = tmp;
    }

    CP_WAIT0();
    __syncthreads();  // sT aliases buffers; all mma done

    #pragma unroll
    for (int jf = 0; jf < 8; jf++) {
        const int oc = 64 * whi + 8 * jf + 2 * t;
        float b0v, b1v;
        if (ot == 0) {
            if (whi == 0) { b0v = __ldg(&bk[oc]);      b1v = __ldg(&bk[oc + 1]); }
            else          { b0v = __ldg(&bv[oc - 64]); b1v = __ldg(&bv[oc - 63]); }
        } else {
            b0v = __ldg(&bq[(ot - 1) * 128 + oc]);
            b1v = __ldg(&bq[(ot - 1) * 128 + oc + 1]);
        }
        #pragma unroll
        for (int fi = 0; fi < 2; fi++) {
            const int r = 32 * wlo + 16 * fi + g;
            const float* d = acc[fi * 8 + jf];
            float v00 = d[0] + b0v;
            float v01 = d[1] + b1v;
            float v10 = d[2] + b0v;
            float v11 = d[3] + b1v;
            if (ot == 0) {
                if (whi == 0) {
                    g_K[(size_t)(row0 + r) * CR_ + oc]         = __float2bfloat16_rn(v00);
                    g_K[(size_t)(row0 + r) * CR_ + oc + 1]     = __float2bfloat16_rn(v01);
                    g_K[(size_t)(row0 + r + 8) * CR_ + oc]     = __float2bfloat16_rn(v10);
                    g_K[(size_t)(row0 + r + 8) * CR_ + oc + 1] = __float2bfloat16_rn(v11);
                } else {
                    const int vc = oc - 64;
                    g_V[(size_t)(row0 + r) * CR_ + vc]         = __float2bfloat16_rn(v00);
                    g_V[(size_t)(row0 + r) * CR_ + vc + 1]     = __float2bfloat16_rn(v01);
                    g_V[(size_t)(row0 + r + 8) * CR_ + vc]     = __float2bfloat16_rn(v10);
                    g_V[(size_t)(row0 + r + 8) * CR_ + vc + 1] = __float2bfloat16_rn(v11);
                }
            } else {
                sT[oc * 132 + r]           = v00;
                sT[(oc + 1) * 132 + r]     = v01;
                sT[oc * 132 + r + 8]       = v10;
                sT[(oc + 1) * 132 + r + 8] = v11;
            }
        }
    }

    if (ot >= 1) {
        __syncthreads();
        const int b  = row0 >> 11;
        const int n0 = row0 & (N_ - 1);
        const size_t qrow0 = (size_t)b * C_ + (ot - 1) * 128;
        #pragma unroll
        for (int l = 0; l < 16; l++) {
            int idx = tid + l * 256;
            int o = idx >> 5, r4 = (idx & 31) << 2;
            float4 v = *(const float4*)&sT[o * 132 + r4];
            uchar4 u;
            u.x = f2e4m3(v.x); u.y = f2e4m3(v.y);
            u.z = f2e4m3(v.z); u.w = f2e4m3(v.w);
            *(uchar4*)&g_Q8[(qrow0 + o) * N_ + n0 + r4] = u;
        }
    }
}

// =======================================================================
// Kernel 2: S = K@V^T (bf16), P = exp(S) -> e4m3, partial den.
// K ring-3, sPT8 x2, copy-out pipelined one iter behind.
// =======================================================================
#define KVB   (64 * PITCH * 2)   // 9216 B
#define P8B   (64 * 80)          // 5120 B
#define PX_SV  0
#define PX_SK  (PX_SV + KVB)            // 3 K slots
#define PX_SPT (PX_SK + 3 * KVB)        // 2 sPT8 buffers
#define PX_DEN (PX_SPT + 2 * P8B)
#define PX_SMEM_BYTES (PX_DEN + 256)
__global__ __launch_bounds__(256, 2) void pexp_kernel()
{
    extern __shared__ char smc[];
    float* sDen = (float*)(smc + PX_DEN);

    const uint32_t smu = smem_u32(smc);
    const uint32_t sVu = smu + PX_SV;
    const uint32_t sKu = smu + PX_SK;

    const int tid = threadIdx.x;
    const int wid = tid >> 5, lane = tid & 31;
    const int g = lane >> 2, t = lane & 3;
    const int wlo = wid & 3;
    const int whi = wid >> 2;
    const int lrow = lane & 15;
    const int lcol = (lane >> 4) << 3;

    const int mt = blockIdx.x, nr = blockIdx.y, b = blockIdx.z;
    const int m0 = mt * 64;
    const size_t rb = (size_t)b * N_;
    const size_t pbase = (size_t)b * N_ * N_;

    if (tid < 64) sDen[tid] = 0.f;

    #pragma unroll
    for (int l = 0; l < 2; l++) {
        int idx = tid + l * 256;
        int r = idx >> 3, ch = idx & 7;
        cp16(sVu + r * 144 + ch * 16, &g_V[(rb + m0 + r) * CR_ + ch * 8]);
        cp16(sKu + r * 144 + ch * 16, &g_K[(rb + nr * 512 + r) * CR_ + ch * 8]);
    }
    CP_COMMIT();
    #pragma unroll
    for (int l = 0; l < 2; l++) {
        int idx = tid + l * 256;
        int r = idx >> 3, ch = idx & 7;
        cp16(sKu + KVB + r * 144 + ch * 16, &g_K[(rb + nr * 512 + 64 + r) * CR_ + ch * 8]);
    }
    CP_COMMIT();

    float den[8];
    #pragma unroll
    for (int i = 0; i < 8; i++) den[i] = 0.f;

    uint32_t k0 = 0, k1 = 1, k2 = 2;
    for (int i = 0; i < 8; i++) {
        CP_WAIT1();
        __syncthreads();

        if (i > 0) {
            const unsigned char* spOld =
                (const unsigned char*)(smc + PX_SPT + ((i - 1) & 1) * P8B);
            const int nOld = nr * 512 + (i - 1) * 64;
            int r = tid >> 2, ch = tid & 3;
            float4 v = *(const float4*)(spOld + r * 80 + ch * 16);
            *(float4*)&g_P8[pbase + (size_t)(m0 + r) * N_ + nOld + ch * 16] = v;
        }

        if (i + 2 < 8) {
            const int nn = nr * 512 + (i + 2) * 64;
            const uint32_t kb = sKu + k2 * KVB;
            #pragma unroll
            for (int l = 0; l < 2; l++) {
                int idx = tid + l * 256;
                int r = idx >> 3, ch = idx & 7;
                cp16(kb + r * 144 + ch * 16, &g_K[(rb + nn + r) * CR_ + ch * 8]);
            }
        }
        CP_COMMIT();

        const uint32_t Kb = sKu + k0 * KVB;

        float sacc[4][4];
        #pragma unroll
        for (int ii = 0; ii < 4; ii++)
            #pragma unroll
            for (int j = 0; j < 4; j++) sacc[ii][j] = 0.f;

        #pragma unroll
        for (int kk = 0; kk < 64; kk += 16) {
            uint32_t a[4], bv0[4], bv1[4];
            ldm4(a,   Kb  + ((16 * wlo + lrow) * PITCH + kk + lcol) * 2);
            ldm4(bv0, sVu + ((32 * whi + lrow) * PITCH + kk + lcol) * 2);
            ldm4(bv1, sVu + ((32 * whi + 16 + lrow) * PITCH + kk + lcol) * 2);
            mma16(sacc[0], a, bv0[0], bv0[2]);
            mma16(sacc[1], a, bv0[1], bv0[3]);
            mma16(sacc[2], a, bv1[0], bv1[2]);
            mma16(sacc[3], a, bv1[1], bv1[3]);
        }

        unsigned char* sPT8 = (unsigned char*)(smc + PX_SPT + (i & 1) * P8B);
        const int nloc = 16 * wlo + g;
        #pragma unroll
        for (int jf = 0; jf < 4; jf++) {
            const int mc = 32 * whi + 8 * jf + 2 * t;
            float e00 = __expf(sacc[jf][0]);
            float e01 = __expf(sacc[jf][1]);
            float e10 = __expf(sacc[jf][2]);
            float e11 = __expf(sacc[jf][3]);
            den[2 * jf]     += e00 + e10;
            den[2 * jf + 1] += e01 + e11;
            sPT8[mc * 80 + nloc]           = f2e4m3(e00);
            sPT8[(mc + 1) * 80 + nloc]     = f2e4m3(e01);
            sPT8[mc * 80 + nloc + 8]       = f2e4m3(e10);
            sPT8[(mc + 1) * 80 + nloc + 8] = f2e4m3(e11);
        }

        uint32_t tmp = k0; k0 = k1; k1 = k2; k2 = tmp;
    }

    __syncthreads();
    {
        const unsigned char* spOld = (const unsigned char*)(smc + PX_SPT + P8B);
        const int nOld = nr * 512 + 7 * 64;
        int r = tid >> 2, ch = tid & 3;
        float4 v = *(const float4*)(spOld + r * 80 + ch * 16);
        *(float4*)&g_P8[pbase + (size_t)(m0 + r) * N_ + nOld + ch * 16] = v;
    }

    #pragma unroll
    for (int jf = 0; jf < 4; jf++) {
        const int mc = 32 * whi + 8 * jf + 2 * t;
        atomicAdd(&sDen[mc],     den[2 * jf]);
        atomicAdd(&sDen[mc + 1], den[2 * jf + 1]);
    }
    __syncthreads();
    if (tid < 64)
        g_denp[(size_t)(b * 4 + nr) * N_ + m0 + tid] = sDen[tid];
}

// =======================================================================
// Kernel 3: attn2 — fp8 e4m3 GEMM: Acc[c 128][m 128] = Qt @ P^T.
// 512 threads (16 warps, warp tile 32c x 32m), ring-3, 3 CTAs/SM target
// (48 warps/SM). grid (16 m-tiles, 4 c-tiles, 8 b).
// =======================================================================
#define P8PITCH 80
#define TB8 (128 * P8PITCH)       // 10240 B per 128-row fp8 tile
#define A2_P  0
#define A2_Q  (A2_P + 3 * TB8)
#define A2_SMEM_BYTES (A2_Q + 3 * TB8)   // 61440
#define NT2 32
__global__ __launch_bounds__(512, 3) void attn2_kernel(
    const float* __restrict__ x, const float* __restrict__ gamma_p,
    float* __restrict__ out)
{
    extern __shared__ char smc[];
    const uint32_t smu = smem_u32(smc);
    const uint32_t sPu = smu + A2_P;
    const uint32_t sQu = smu + A2_Q;

    const int tid = threadIdx.x;
    const int wid = tid >> 5, lane = tid & 31;
    const int g = lane >> 2, t = lane & 3;
    const int wlo = wid & 3;        // c group (32): 4 x 32 = 128c
    const int whi = wid >> 2;       // m group (32): 4 x 32 = 128m

    const int arow = lane & 15;
    const int acol = (lane >> 4) << 4;
    const int brow = (lane & 7) | ((lane >> 4) << 3);
    const int bcol = ((lane >> 3) & 1) << 4;

    const uint32_t aoff0 = (32 * wlo + arow) * P8PITCH + acol;
    const uint32_t aoff1 = aoff0 + 16 * P8PITCH;
    const uint32_t boff0 = (32 * whi + brow) * P8PITCH + bcol;
    const uint32_t boff1 = boff0 + 16 * P8PITCH;

    const int mt = blockIdx.x, ct = blockIdx.y, b = blockIdx.z;
    const int m0 = mt * 128, c0 = ct * 128;
    const size_t rb = (size_t)b * N_;

    // per-thread load slots: 512 threads cover 128 rows x 4 16B-chunks
    const int lr = tid >> 2, lch = tid & 3;
    const unsigned char* gP = &g_P8[(size_t)b * N_ * N_ + (size_t)(m0 + lr) * N_ + lch * 16];
    const unsigned char* gQ = &g_Q8[((size_t)b * C_ + c0 + lr) * N_ + lch * 16];
    const uint32_t pdst = sPu + lr * P8PITCH + lch * 16;
    const uint32_t qdst = sQu + lr * P8PITCH + lch * 16;

    // prologue: stages 0,1
    #pragma unroll
    for (int s = 0; s < 2; s++) {
        cp16(pdst + s * TB8, gP + s * 64);
        cp16(qdst + s * TB8, gQ + s * 64);
        CP_COMMIT();
    }
    gP += 128; gQ += 128;

    float acc[8][4];   // [fi*4 + mj]
    #pragma unroll
    for (int i = 0; i < 8; i++)
        #pragma unroll
        for (int j = 0; j < 4; j++) acc[i][j] = 0.f;

    uint32_t sl0 = 0, sl1 = 1, sl2 = 2;
    for (int nt = 0; nt < NT2; nt++) {
        CP_WAIT1();
        __syncthreads();

        if (nt + 2 < NT2) {
            cp16(pdst + sl2 * TB8, gP);
            cp16(qdst + sl2 * TB8, gQ);
            gP += 64; gQ += 64;
        }
        CP_COMMIT();

        const uint32_t Pb = sPu + sl0 * TB8;
        const uint32_t Qb = sQu + sl0 * TB8;

        #pragma unroll
        for (int kk = 0; kk < 64; kk += 32) {
            uint32_t a0[4], a1[4], p0[4], p1[4];
            ldm4(a0, Qb + aoff0 + kk);
            ldm4(a1, Qb + aoff1 + kk);
            ldm4(p0, Pb + boff0 + kk);
            ldm4(p1, Pb + boff1 + kk);
            mma32(acc[0], a0, p0[0], p0[1]);
            mma32(acc[1], a0, p0[2], p0[3]);
            mma32(acc[2], a0, p1[0], p1[1]);
            mma32(acc[3], a0, p1[2], p1[3]);
            mma32(acc[4], a1, p0[0], p0[1]);
            mma32(acc[5], a1, p0[2], p0[3]);
            mma32(acc[6], a1, p1[0], p1[1]);
            mma32(acc[7], a1, p1[2], p1[3]);
        }

        uint32_t tmp = sl0; sl0 = sl1; sl1 = sl2; sl2 = tmp;
    }

    // ---- epilogue: out = gamma*Acc/den + x ----
    const float gam = gamma_p[0];
    #pragma unroll
    for (int mj = 0; mj < 4; mj++) {
        const int mc = 32 * whi + 8 * mj + 2 * t;
        float d0 = 0.f, d1 = 0.f;
        #pragma unroll
        for (int nr = 0; nr < 4; nr++) {
            d0 += __ldg(&g_denp[(size_t)(b * 4 + nr) * N_ + m0 + mc]);
            d1 += __ldg(&g_denp[(size_t)(b * 4 + nr) * N_ + m0 + mc + 1]);
        }
        const float di0 = gam / d0;
        const float di1 = gam / d1;
        #pragma unroll
        for (int fi = 0; fi < 2; fi++) {
            const int cc = c0 + 32 * wlo + 16 * fi + g;
            const size_t r0a = (rb + m0 + mc) * C_ + cc;
            const size_t r1a = (rb + m0 + mc + 1) * C_ + cc;
            const float* d = acc[fi * 4 + mj];
            out[r0a]     = d[0] * di0 + __ldg(&x[r0a]);
            out[r1a]     = d[1] * di1 + __ldg(&x[r1a]);
            out[r0a + 8] = d[2] * di0 + __ldg(&x[r0a + 8]);
            out[r1a + 8] = d[3] * di1 + __ldg(&x[r1a + 8]);
        }
    }
}

// =======================================================================
extern "C" void kernel_launch(void* const* d_in, const int* in_sizes, int n_in,
                              void* d_out, int out_size)
{
    const float* x     = (const float*)d_in[0];
    const float* Wk    = (const float*)d_in[1];
    const float* bk    = (const float*)d_in[2];
    const float* Wv    = (const float*)d_in[3];
    const float* bv    = (const float*)d_in[4];
    const float* Wq    = (const float*)d_in[5];
    const float* bq    = (const float*)d_in[6];
    const float* gamma = (const float*)d_in[7];
    float* out = (float*)d_out;

    cudaFuncSetAttribute(proj_hmma,    cudaFuncAttributeMaxDynamicSharedMemorySize, PJ_SMEM_BYTES);
    cudaFuncSetAttribute(pexp_kernel,  cudaFuncAttributeMaxDynamicSharedMemorySize, PX_SMEM_BYTES);
    cudaFuncSetAttribute(attn2_kernel, cudaFuncAttributeMaxDynamicSharedMemorySize, A2_SMEM_BYTES);

    cvt_kernel<<<1184, 256>>>(x, Wk, Wv, Wq);
    proj_hmma<<<dim3(5, 128), 256, PJ_SMEM_BYTES>>>(bk, bv, bq);
    pexp_kernel<<<dim3(32, 4, B_), 256, PX_SMEM_BYTES>>>();
    attn2_kernel<<<dim3(16, 4, B_), 512, A2_SMEM_BYTES>>>(x, gamma, out);
}

// round 15
// speedup vs baseline: 1.6930x; 1.6930x over previous
#include <cuda_runtime.h>
#include <cuda_bf16.h>
#include <cuda_fp8.h>
#include <cstdint>

#define B_  8
#define N_  2048
#define C_  512
#define CR_ 64

// Device-global scratch (no allocs allowed).
__device__ __nv_bfloat16 g_xb[(size_t)B_ * N_ * C_];    // x in bf16
__device__ __nv_bfloat16 g_Wb[(size_t)640 * C_];        // [Wk;Wv;Wq] bf16
__device__ __nv_bfloat16 g_K [(size_t)B_ * N_ * CR_];   // [b*N+n][64]
__device__ __nv_bfloat16 g_V [(size_t)B_ * N_ * CR_];   // [b*N+m][64]
__device__ unsigned char g_Q8[(size_t)B_ * C_ * N_];    // Qt e4m3: [b*C+c][n]
__device__ unsigned char g_P8[(size_t)B_ * N_ * N_];    // P^T e4m3: [b][m][n]
__device__ float         g_denp[(size_t)B_ * 4 * N_];   // partial den

__device__ __forceinline__ uint32_t smem_u32(const void* p) {
    uint32_t a;
    asm("{ .reg .u64 t; cvta.to.shared.u64 t, %1; cvt.u32.u64 %0, t; }" : "=r"(a) : "l"(p));
    return a;
}
__device__ __forceinline__ void cp16(uint32_t dst, const void* src) {
    asm volatile("cp.async.cg.shared.global [%0], [%1], 16;" :: "r"(dst), "l"(src));
}
#define CP_COMMIT() asm volatile("cp.async.commit_group;" ::: "memory")
#define CP_WAIT0()  asm volatile("cp.async.wait_group 0;"  ::: "memory")
#define CP_WAIT1()  asm volatile("cp.async.wait_group 1;"  ::: "memory")

__device__ __forceinline__ unsigned char f2e4m3(float f) {
    return (unsigned char)__nv_cvt_float_to_fp8(f, __NV_SATFINITE, __NV_E4M3);
}

// bf16 warp mma: D(16x8) += A(16x16)*B(16x8)
__device__ __forceinline__ void mma16(float d[4], const uint32_t a[4], uint32_t b0, uint32_t b1) {
    asm volatile(
        "mma.sync.aligned.m16n8k16.row.col.f32.bf16.bf16.f32 "
        "{%0,%1,%2,%3}, {%4,%5,%6,%7}, {%8,%9}, {%0,%1,%2,%3};"
        : "+f"(d[0]), "+f"(d[1]), "+f"(d[2]), "+f"(d[3])
        : "r"(a[0]), "r"(a[1]), "r"(a[2]), "r"(a[3]), "r"(b0), "r"(b1));
}
// fp8 warp mma: D(16x8) += A(16x32)*B(32x8), e4m3
__device__ __forceinline__ void mma32(float d[4], const uint32_t a[4], uint32_t b0, uint32_t b1) {
    asm volatile(
        "mma.sync.aligned.m16n8k32.row.col.f32.e4m3.e4m3.f32 "
        "{%0,%1,%2,%3}, {%4,%5,%6,%7}, {%8,%9}, {%0,%1,%2,%3};"
        : "+f"(d[0]), "+f"(d[1]), "+f"(d[2]), "+f"(d[3])
        : "r"(a[0]), "r"(a[1]), "r"(a[2]), "r"(a[3]), "r"(b0), "r"(b1));
}
__device__ __forceinline__ void ldm4(uint32_t r[4], uint32_t addr) {
    asm volatile("ldmatrix.sync.aligned.m8n8.x4.shared.b16 {%0,%1,%2,%3}, [%4];"
        : "=r"(r[0]), "=r"(r[1]), "=r"(r[2]), "=r"(r[3]) : "r"(addr));
}

// =======================================================================
// Kernel 0: fp32 -> bf16 conversion of x and [Wk;Wv;Wq].
// =======================================================================
__global__ __launch_bounds__(256) void cvt_kernel(
    const float* __restrict__ x,
    const float* __restrict__ Wk, const float* __restrict__ Wv,
    const float* __restrict__ Wq)
{
    const int NX = (B_ * N_ * C_) / 4;
    const int NW = (640 * C_) / 4;
    for (int i = blockIdx.x * blockDim.x + threadIdx.x; i < NX + NW;
         i += gridDim.x * blockDim.x) {
        float4 v;
        __nv_bfloat16* dst;
        if (i < NX) {
            v = ((const float4*)x)[i];
            dst = &g_xb[(size_t)i * 4];
        } else {
            int j = i - NX;
            const int row = (j * 4) / C_;
            const float* src;
            if (row < 64)        src = Wk;
            else if (row < 128)  src = Wv - 64 * C_;
            else                 src = Wq - 128 * C_;
            v = ((const float4*)src)[j];
            dst = &g_Wb[(size_t)j * 4];
        }
        __nv_bfloat162 p0 = __floats2bfloat162_rn(v.x, v.y);
        __nv_bfloat162 p1 = __floats2bfloat162_rn(v.z, v.w);
        ((__nv_bfloat162*)dst)[0] = p0;
        ((__nv_bfloat162*)dst)[1] = p1;
    }
}

// =======================================================================
// Kernel 1: projection GEMM (bf16 HMMA + ldmatrix), 128x128 tiles,
// ring-3, 1 barrier/iter. grid (5 o-tiles of 128, 128 row-tiles of 128).
// ot 0 -> K(64)+V(64); ot 1..4 -> Qt e4m3 (transposed), 128 chans each.
// =======================================================================
#define PITCH 72
#define PAB (128 * PITCH * 2)   // 18432 B per 128-row tile
#define PJ_A 0
#define PJ_B (PJ_A + 3 * PAB)
#define PJ_SMEM_BYTES (PJ_B + 3 * PAB)   // 110592
__global__ __launch_bounds__(256, 2) void proj_hmma(
    const float* __restrict__ bk, const float* __restrict__ bv,
    const float* __restrict__ bq)
{
    extern __shared__ char smc[];
    float* sT = (float*)smc;   // staging [128 oc][132 r] floats

    const uint32_t smu = smem_u32(smc);
    const uint32_t sAu = smu + PJ_A, sBu = smu + PJ_B;

    const int tid = threadIdx.x;
    const int wid = tid >> 5, lane = tid & 31;
    const int g = lane >> 2, t = lane & 3;
    const int wlo = wid & 3;        // row group (32 of 128)
    const int whi = wid >> 2;       // o group (64 of 128)
    const int lrow = lane & 15;
    const int lcol = (lane >> 4) << 3;

    const int ot = blockIdx.x;      // 0..4
    const int row0 = blockIdx.y * 128;
    const int wrow0 = ot * 128;

    #pragma unroll
    for (int pf = 0; pf < 2; pf++) {
        const int kc = pf * 64;
        const uint32_t ab = sAu + pf * PAB, bb = sBu + pf * PAB;
        #pragma unroll
        for (int l = 0; l < 4; l++) {
            int idx = tid + l * 256;
            int r = idx >> 3, ch = idx & 7;
            cp16(ab + r * 144 + ch * 16, &g_xb[(size_t)(row0 + r) * C_ + kc + ch * 8]);
            cp16(bb + r * 144 + ch * 16, &g_Wb[(size_t)(wrow0 + r) * C_ + kc + ch * 8]);
        }
        CP_COMMIT();
    }

    float acc[16][4];
    #pragma unroll
    for (int i = 0; i < 16; i++)
        #pragma unroll
        for (int j = 0; j < 4; j++) acc[i][j] = 0.f;

    const uint32_t aoff0 = ((32 * wlo + lrow) * PITCH + lcol) * 2;
    const uint32_t aoff1 = aoff0 + 16 * PITCH * 2;
    const uint32_t boff0 = ((64 * whi + lrow) * PITCH + lcol) * 2;
    const uint32_t boff1 = boff0 + 16 * PITCH * 2;
    const uint32_t boff2 = boff0 + 32 * PITCH * 2;
    const uint32_t boff3 = boff0 + 48 * PITCH * 2;

    uint32_t sl0 = 0, sl1 = 1, sl2 = 2;
    for (int it = 0; it < 8; it++) {
        CP_WAIT1();
        __syncthreads();

        if (it + 2 < 8) {
            const int kc = (it + 2) * 64;
            const uint32_t ab = sAu + sl2 * PAB, bb = sBu + sl2 * PAB;
            #pragma unroll
            for (int l = 0; l < 4; l++) {
                int idx = tid + l * 256;
                int r = idx >> 3, ch = idx & 7;
                cp16(ab + r * 144 + ch * 16, &g_xb[(size_t)(row0 + r) * C_ + kc + ch * 8]);
                cp16(bb + r * 144 + ch * 16, &g_Wb[(size_t)(wrow0 + r) * C_ + kc + ch * 8]);
            }
        }
        CP_COMMIT();

        const uint32_t Ab = sAu + sl0 * PAB;
        const uint32_t Bb = sBu + sl0 * PAB;

        #pragma unroll
        for (int kk = 0; kk < 64; kk += 16) {
            uint32_t a0[4], a1[4], b0[4], b1[4], b2[4], b3[4];
            ldm4(a0, Ab + aoff0 + kk * 2);
            ldm4(a1, Ab + aoff1 + kk * 2);
            ldm4(b0, Bb + boff0 + kk * 2);
            ldm4(b1, Bb + boff1 + kk * 2);
            ldm4(b2, Bb + boff2 + kk * 2);
            ldm4(b3, Bb + boff3 + kk * 2);
            mma16(acc[0],  a0, b0[0], b0[2]);
            mma16(acc[1],  a0, b0[1], b0[3]);
            mma16(acc[2],  a0, b1[0], b1[2]);
            mma16(acc[3],  a0, b1[1], b1[3]);
            mma16(acc[4],  a0, b2[0], b2[2]);
            mma16(acc[5],  a0, b2[1], b2[3]);
            mma16(acc[6],  a0, b3[0], b3[2]);
            mma16(acc[7],  a0, b3[1], b3[3]);
            mma16(acc[8],  a1, b0[0], b0[2]);
            mma16(acc[9],  a1, b0[1], b0[3]);
            mma16(acc[10], a1, b1[0], b1[2]);
            mma16(acc[11], a1, b1[1], b1[3]);
            mma16(acc[12], a1, b2[0], b2[2]);
            mma16(acc[13], a1, b2[1], b2[3]);
            mma16(acc[14], a1, b3[0], b3[2]);
            mma16(acc[15], a1, b3[1], b3[3]);
        }

        uint32_t tmp = sl0; sl0 = sl1; sl1 = sl2; sl2 = tmp;
    }

    CP_WAIT0();
    __syncthreads();  // sT aliases buffers; all mma done

    #pragma unroll
    for (int jf = 0; jf < 8; jf++) {
        const int oc = 64 * whi + 8 * jf + 2 * t;
        float b0v, b1v;
        if (ot == 0) {
            if (whi == 0) { b0v = __ldg(&bk[oc]);      b1v = __ldg(&bk[oc + 1]); }
            else          { b0v = __ldg(&bv[oc - 64]); b1v = __ldg(&bv[oc - 63]); }
        } else {
            b0v = __ldg(&bq[(ot - 1) * 128 + oc]);
            b1v = __ldg(&bq[(ot - 1) * 128 + oc + 1]);
        }
        #pragma unroll
        for (int fi = 0; fi < 2; fi++) {
            const int r = 32 * wlo + 16 * fi + g;
            const float* d = acc[fi * 8 + jf];
            float v00 = d[0] + b0v;
            float v01 = d[1] + b1v;
            float v10 = d[2] + b0v;
            float v11 = d[3] + b1v;
            if (ot == 0) {
                if (whi == 0) {
                    g_K[(size_t)(row0 + r) * CR_ + oc]         = __float2bfloat16_rn(v00);
                    g_K[(size_t)(row0 + r) * CR_ + oc + 1]     = __float2bfloat16_rn(v01);
                    g_K[(size_t)(row0 + r + 8) * CR_ + oc]     = __float2bfloat16_rn(v10);
                    g_K[(size_t)(row0 + r + 8) * CR_ + oc + 1] = __float2bfloat16_rn(v11);
                } else {
                    const int vc = oc - 64;
                    g_V[(size_t)(row0 + r) * CR_ + vc]         = __float2bfloat16_rn(v00);
                    g_V[(size_t)(row0 + r) * CR_ + vc + 1]     = __float2bfloat16_rn(v01);
                    g_V[(size_t)(row0 + r + 8) * CR_ + vc]     = __float2bfloat16_rn(v10);
                    g_V[(size_t)(row0 + r + 8) * CR_ + vc + 1] = __float2bfloat16_rn(v11);
                }
            } else {
                sT[oc * 132 + r]           = v00;
                sT[(oc + 1) * 132 + r]     = v01;
                sT[oc * 132 + r + 8]       = v10;
                sT[(oc + 1) * 132 + r + 8] = v11;
            }
        }
    }

    if (ot >= 1) {
        __syncthreads();
        const int b  = row0 >> 11;
        const int n0 = row0 & (N_ - 1);
        const size_t qrow0 = (size_t)b * C_ + (ot - 1) * 128;
        #pragma unroll
        for (int l = 0; l < 16; l++) {
            int idx = tid + l * 256;
            int o = idx >> 5, r4 = (idx & 31) << 2;
            float4 v = *(const float4*)&sT[o * 132 + r4];
            uchar4 u;
            u.x = f2e4m3(v.x); u.y = f2e4m3(v.y);
            u.z = f2e4m3(v.z); u.w = f2e4m3(v.w);
            *(uchar4*)&g_Q8[(qrow0 + o) * N_ + n0 + r4] = u;
        }
    }
}

// =======================================================================
// Kernel 2: S = K@V^T (bf16), P = exp(S) -> e4m3, partial den.
// K ring-3, sPT8 x2, copy-out pipelined one iter behind.
// =======================================================================
#define KVB   (64 * PITCH * 2)   // 9216 B
#define P8B   (64 * 80)          // 5120 B
#define PX_SV  0
#define PX_SK  (PX_SV + KVB)            // 3 K slots
#define PX_SPT (PX_SK + 3 * KVB)        // 2 sPT8 buffers
#define PX_DEN (PX_SPT + 2 * P8B)
#define PX_SMEM_BYTES (PX_DEN + 256)
__global__ __launch_bounds__(256, 2) void pexp_kernel()
{
    extern __shared__ char smc[];
    float* sDen = (float*)(smc + PX_DEN);

    const uint32_t smu = smem_u32(smc);
    const uint32_t sVu = smu + PX_SV;
    const uint32_t sKu = smu + PX_SK;

    const int tid = threadIdx.x;
    const int wid = tid >> 5, lane = tid & 31;
    const int g = lane >> 2, t = lane & 3;
    const int wlo = wid & 3;
    const int whi = wid >> 2;
    const int lrow = lane & 15;
    const int lcol = (lane >> 4) << 3;

    const int mt = blockIdx.x, nr = blockIdx.y, b = blockIdx.z;
    const int m0 = mt * 64;
    const size_t rb = (size_t)b * N_;
    const size_t pbase = (size_t)b * N_ * N_;

    if (tid < 64) sDen[tid] = 0.f;

    #pragma unroll
    for (int l = 0; l < 2; l++) {
        int idx = tid + l * 256;
        int r = idx >> 3, ch = idx & 7;
        cp16(sVu + r * 144 + ch * 16, &g_V[(rb + m0 + r) * CR_ + ch * 8]);
        cp16(sKu + r * 144 + ch * 16, &g_K[(rb + nr * 512 + r) * CR_ + ch * 8]);
    }
    CP_COMMIT();
    #pragma unroll
    for (int l = 0; l < 2; l++) {
        int idx = tid + l * 256;
        int r = idx >> 3, ch = idx & 7;
        cp16(sKu + KVB + r * 144 + ch * 16, &g_K[(rb + nr * 512 + 64 + r) * CR_ + ch * 8]);
    }
    CP_COMMIT();

    float den[8];
    #pragma unroll
    for (int i = 0; i < 8; i++) den[i] = 0.f;

    uint32_t k0 = 0, k1 = 1, k2 = 2;
    for (int i = 0; i < 8; i++) {
        CP_WAIT1();
        __syncthreads();

        if (i > 0) {
            const unsigned char* spOld =
                (const unsigned char*)(smc + PX_SPT + ((i - 1) & 1) * P8B);
            const int nOld = nr * 512 + (i - 1) * 64;
            int r = tid >> 2, ch = tid & 3;
            float4 v = *(const float4*)(spOld + r * 80 + ch * 16);
            *(float4*)&g_P8[pbase + (size_t)(m0 + r) * N_ + nOld + ch * 16] = v;
        }

        if (i + 2 < 8) {
            const int nn = nr * 512 + (i + 2) * 64;
            const uint32_t kb = sKu + k2 * KVB;
            #pragma unroll
            for (int l = 0; l < 2; l++) {
                int idx = tid + l * 256;
                int r = idx >> 3, ch = idx & 7;
                cp16(kb + r * 144 + ch * 16, &g_K[(rb + nn + r) * CR_ + ch * 8]);
            }
        }
        CP_COMMIT();

        const uint32_t Kb = sKu + k0 * KVB;

        float sacc[4][4];
        #pragma unroll
        for (int ii = 0; ii < 4; ii++)
            #pragma unroll
            for (int j = 0; j < 4; j++) sacc[ii][j] = 0.f;

        #pragma unroll
        for (int kk = 0; kk < 64; kk += 16) {
            uint32_t a[4], bv0[4], bv1[4];
            ldm4(a,   Kb  + ((16 * wlo + lrow) * PITCH + kk + lcol) * 2);
            ldm4(bv0, sVu + ((32 * whi + lrow) * PITCH + kk + lcol) * 2);
            ldm4(bv1, sVu + ((32 * whi + 16 + lrow) * PITCH + kk + lcol) * 2);
            mma16(sacc[0], a, bv0[0], bv0[2]);
            mma16(sacc[1], a, bv0[1], bv0[3]);
            mma16(sacc[2], a, bv1[0], bv1[2]);
            mma16(sacc[3], a, bv1[1], bv1[3]);
        }

        unsigned char* sPT8 = (unsigned char*)(smc + PX_SPT + (i & 1) * P8B);
        const int nloc = 16 * wlo + g;
        #pragma unroll
        for (int jf = 0; jf < 4; jf++) {
            const int mc = 32 * whi + 8 * jf + 2 * t;
            float e00 = __expf(sacc[jf][0]);
            float e01 = __expf(sacc[jf][1]);
            float e10 = __expf(sacc[jf][2]);
            float e11 = __expf(sacc[jf][3]);
            den[2 * jf]     += e00 + e10;
            den[2 * jf + 1] += e01 + e11;
            sPT8[mc * 80 + nloc]           = f2e4m3(e00);
            sPT8[(mc + 1) * 80 + nloc]     = f2e4m3(e01);
            sPT8[mc * 80 + nloc + 8]       = f2e4m3(e10);
            sPT8[(mc + 1) * 80 + nloc + 8] = f2e4m3(e11);
        }

        uint32_t tmp = k0; k0 = k1; k1 = k2; k2 = tmp;
    }

    __syncthreads();
    {
        const unsigned char* spOld = (const unsigned char*)(smc + PX_SPT + P8B);
        const int nOld = nr * 512 + 7 * 64;
        int r = tid >> 2, ch = tid & 3;
        float4 v = *(const float4*)(spOld + r * 80 + ch * 16);
        *(float4*)&g_P8[pbase + (size_t)(m0 + r) * N_ + nOld + ch * 16] = v;
    }

    #pragma unroll
    for (int jf = 0; jf < 4; jf++) {
        const int mc = 32 * whi + 8 * jf + 2 * t;
        atomicAdd(&sDen[mc],     den[2 * jf]);
        atomicAdd(&sDen[mc + 1], den[2 * jf + 1]);
    }
    __syncthreads();
    if (tid < 64)
        g_denp[(size_t)(b * 4 + nr) * N_ + m0 + tid] = sDen[tid];
}

// =======================================================================
// Kernel 3: attn2 — fp8 e4m3 GEMM: Acc[c 128][m 64] = Qt @ P^T.
// grid (32 m-tiles, 4 c-tiles, 8 b), ring-3, occupancy 4 (regs<=64).
// =======================================================================
#define P8PITCH 80
#define PB8 (64  * P8PITCH)
#define QB8 (128 * P8PITCH)
#define A2_P  0
#define A2_Q  (A2_P + 3 * PB8)
#define A2_SMEM_BYTES (A2_Q + 3 * QB8)   // 46080
#define NT2 32
__global__ __launch_bounds__(256, 4) void attn2_kernel(
    const float* __restrict__ x, const float* __restrict__ gamma_p,
    float* __restrict__ out)
{
    extern __shared__ char smc[];
    const uint32_t smu = smem_u32(smc);
    const uint32_t sPu = smu + A2_P;
    const uint32_t sQu = smu + A2_Q;

    const int tid = threadIdx.x;
    const int wid = tid >> 5, lane = tid & 31;
    const int g = lane >> 2, t = lane & 3;
    const int wlo = wid & 3;
    const int whi = wid >> 2;

    const int arow = lane & 15;
    const int acol = (lane >> 4) << 4;
    const int brow = (lane & 7) | ((lane >> 4) << 3);
    const int bcol = ((lane >> 3) & 1) << 4;

    const uint32_t aoff0 = (32 * wlo + arow) * P8PITCH + acol;
    const uint32_t aoff1 = aoff0 + 16 * P8PITCH;
    const uint32_t boff0 = (32 * whi + brow) * P8PITCH + bcol;
    const uint32_t boff1 = boff0 + 16 * P8PITCH;

    const int mt = blockIdx.x, ct = blockIdx.y, b = blockIdx.z;
    const int m0 = mt * 64, c0 = ct * 128;
    const size_t rb = (size_t)b * N_;

    // incremental prefetch pointers (advance 64 B per stage)
    const unsigned char* gP  = &g_P8[(size_t)b * N_ * N_ + (size_t)(m0 + (tid >> 2)) * N_ + (tid & 3) * 16];
    const unsigned char* gQ0 = &g_Q8[((size_t)b * C_ + c0 + (tid >> 2)) * N_ + (tid & 3) * 16];
    const unsigned char* gQ1 = gQ0 + (size_t)64 * N_;
    const uint32_t pdst  = sPu + (tid >> 2) * P8PITCH + (tid & 3) * 16;
    const uint32_t qdst0 = sQu + (tid >> 2) * P8PITCH + (tid & 3) * 16;
    const uint32_t qdst1 = qdst0 + 64 * P8PITCH;

    // prologue: stages 0,1
    #pragma unroll
    for (int s = 0; s < 2; s++) {
        cp16(pdst  + s * PB8, gP  + s * 64);
        cp16(qdst0 + s * QB8, gQ0 + s * 64);
        cp16(qdst1 + s * QB8, gQ1 + s * 64);
        CP_COMMIT();
    }
    gP += 128; gQ0 += 128; gQ1 += 128;

    float acc[8][4];
    #pragma unroll
    for (int i = 0; i < 8; i++)
        #pragma unroll
        for (int j = 0; j < 4; j++) acc[i][j] = 0.f;

    uint32_t sl0 = 0, sl1 = 1, sl2 = 2;
    for (int nt = 0; nt < NT2; nt++) {
        CP_WAIT1();
        __syncthreads();

        if (nt + 2 < NT2) {
            cp16(pdst  + sl2 * PB8, gP);
            cp16(qdst0 + sl2 * QB8, gQ0);
            cp16(qdst1 + sl2 * QB8, gQ1);
            gP += 64; gQ0 += 64; gQ1 += 64;
        }
        CP_COMMIT();

        const uint32_t Pb = sPu + sl0 * PB8;
        const uint32_t Qb = sQu + sl0 * QB8;

        #pragma unroll
        for (int kk = 0; kk < 64; kk += 32) {
            uint32_t a0[4], a1[4], p0[4], p1[4];
            ldm4(a0, Qb + aoff0 + kk);
            ldm4(a1, Qb + aoff1 + kk);
            ldm4(p0, Pb + boff0 + kk);
            ldm4(p1, Pb + boff1 + kk);
            mma32(acc[0], a0, p0[0], p0[1]);
            mma32(acc[1], a0, p0[2], p0[3]);
            mma32(acc[2], a0, p1[0], p1[1]);
            mma32(acc[3], a0, p1[2], p1[3]);
            mma32(acc[4], a1, p0[0], p0[1]);
            mma32(acc[5], a1, p0[2], p0[3]);
            mma32(acc[6], a1, p1[0], p1[1]);
            mma32(acc[7], a1, p1[2], p1[3]);
        }

        uint32_t tmp = sl0; sl0 = sl1; sl1 = sl2; sl2 = tmp;
    }

    // ---- epilogue ----
    const float gam = gamma_p[0];
    #pragma unroll
    for (int mj = 0; mj < 4; mj++) {
        const int mc = 32 * whi + 8 * mj + 2 * t;
        float d0 = 0.f, d1 = 0.f;
        #pragma unroll
        for (int nr = 0; nr < 4; nr++) {
            d0 += __ldg(&g_denp[(size_t)(b * 4 + nr) * N_ + m0 + mc]);
            d1 += __ldg(&g_denp[(size_t)(b * 4 + nr) * N_ + m0 + mc + 1]);
        }
        const float di0 = gam / d0;
        const float di1 = gam / d1;
        #pragma unroll
        for (int fi = 0; fi < 2; fi++) {
            const int cc = c0 + 32 * wlo + 16 * fi + g;
            const size_t r0a = (rb + m0 + mc) * C_ + cc;
            const size_t r1a = (rb + m0 + mc + 1) * C_ + cc;
            const float* d = acc[fi * 4 + mj];
            out[r0a]     = d[0] * di0 + __ldg(&x[r0a]);
            out[r1a]     = d[1] * di1 + __ldg(&x[r1a]);
            out[r0a + 8] = d[2] * di0 + __ldg(&x[r0a + 8]);
            out[r1a + 8] = d[3] * di1 + __ldg(&x[r1a + 8]);
        }
    }
}

// =======================================================================
extern "C" void kernel_launch(void* const* d_in, const int* in_sizes, int n_in,
                              void* d_out, int out_size)
{
    const float* x     = (const float*)d_in[0];
    const float* Wk    = (const float*)d_in[1];
    const float* bk    = (const float*)d_in[2];
    const float* Wv    = (const float*)d_in[3];
    const float* bv    = (const float*)d_in[4];
    const float* Wq    = (const float*)d_in[5];
    const float* bq    = (const float*)d_in[6];
    const float* gamma = (const float*)d_in[7];
    float* out = (float*)d_out;

    cudaFuncSetAttribute(proj_hmma,    cudaFuncAttributeMaxDynamicSharedMemorySize, PJ_SMEM_BYTES);
    cudaFuncSetAttribute(pexp_kernel,  cudaFuncAttributeMaxDynamicSharedMemorySize, PX_SMEM_BYTES);
    cudaFuncSetAttribute(attn2_kernel, cudaFuncAttributeMaxDynamicSharedMemorySize, A2_SMEM_BYTES);

    cvt_kernel<<<1184, 256>>>(x, Wk, Wv, Wq);
    proj_hmma<<<dim3(5, 128), 256, PJ_SMEM_BYTES>>>(bk, bv, bq);
    pexp_kernel<<<dim3(32, 4, B_), 256, PX_SMEM_BYTES>>>();
    attn2_kernel<<<dim3(32, 4, B_), 256, A2_SMEM_BYTES>>>(x, gamma, out);
}

// round 16
// speedup vs baseline: 2.2131x; 1.3072x over previous
#include <cuda_runtime.h>
#include <cuda_bf16.h>
#include <cuda_fp8.h>
#include <cstdint>

#define B_  8
#define N_  2048
#define C_  512
#define CR_ 64

// Device-global scratch (no allocs allowed).
__device__ __nv_bfloat16 g_xb[(size_t)B_ * N_ * C_];    // x in bf16
__device__ __nv_bfloat16 g_Wb[(size_t)640 * C_];        // [Wk;Wv;Wq] bf16
__device__ __nv_bfloat16 g_K [(size_t)B_ * N_ * CR_];   // [b*N+n][64]
__device__ __nv_bfloat16 g_V [(size_t)B_ * N_ * CR_];   // [b*N+m][64]
__device__ unsigned char g_Q8[(size_t)B_ * C_ * N_];    // Qt e4m3: [b*C+c][n]
__device__ unsigned char g_P8[(size_t)B_ * N_ * N_];    // P^T e4m3: [b][m][n]
__device__ float         g_denp[(size_t)B_ * 4 * N_];   // partial den

__device__ __forceinline__ uint32_t smem_u32(const void* p) {
    uint32_t a;
    asm("{ .reg .u64 t; cvta.to.shared.u64 t, %1; cvt.u32.u64 %0, t; }" : "=r"(a) : "l"(p));
    return a;
}
__device__ __forceinline__ void cp16(uint32_t dst, const void* src) {
    asm volatile("cp.async.cg.shared.global [%0], [%1], 16;" :: "r"(dst), "l"(src));
}
#define CP_COMMIT() asm volatile("cp.async.commit_group;" ::: "memory")
#define CP_WAIT0()  asm volatile("cp.async.wait_group 0;"  ::: "memory")
#define CP_WAIT1()  asm volatile("cp.async.wait_group 1;"  ::: "memory")

__device__ __forceinline__ unsigned char f2e4m3(float f) {
    return (unsigned char)__nv_cvt_float_to_fp8(f, __NV_SATFINITE, __NV_E4M3);
}

// bf16 warp mma: D(16x8) += A(16x16)*B(16x8)
__device__ __forceinline__ void mma16(float d[4], const uint32_t a[4], uint32_t b0, uint32_t b1) {
    asm volatile(
        "mma.sync.aligned.m16n8k16.row.col.f32.bf16.bf16.f32 "
        "{%0,%1,%2,%3}, {%4,%5,%6,%7}, {%8,%9}, {%0,%1,%2,%3};"
        : "+f"(d[0]), "+f"(d[1]), "+f"(d[2]), "+f"(d[3])
        : "r"(a[0]), "r"(a[1]), "r"(a[2]), "r"(a[3]), "r"(b0), "r"(b1));
}
// fp8 warp mma: D(16x8) += A(16x32)*B(32x8), e4m3
__device__ __forceinline__ void mma32(float d[4], const uint32_t a[4], uint32_t b0, uint32_t b1) {
    asm volatile(
        "mma.sync.aligned.m16n8k32.row.col.f32.e4m3.e4m3.f32 "
        "{%0,%1,%2,%3}, {%4,%5,%6,%7}, {%8,%9}, {%0,%1,%2,%3};"
        : "+f"(d[0]), "+f"(d[1]), "+f"(d[2]), "+f"(d[3])
        : "r"(a[0]), "r"(a[1]), "r"(a[2]), "r"(a[3]), "r"(b0), "r"(b1));
}
__device__ __forceinline__ void ldm4(uint32_t r[4], uint32_t addr) {
    asm volatile("ldmatrix.sync.aligned.m8n8.x4.shared.b16 {%0,%1,%2,%3}, [%4];"
        : "=r"(r[0]), "=r"(r[1]), "=r"(r[2]), "=r"(r[3]) : "r"(addr));
}

// =======================================================================
// Kernel 0: fp32 -> bf16 conversion of x and [Wk;Wv;Wq].
// =======================================================================
__global__ __launch_bounds__(256) void cvt_kernel(
    const float* __restrict__ x,
    const float* __restrict__ Wk, const float* __restrict__ Wv,
    const float* __restrict__ Wq)
{
    const int NX = (B_ * N_ * C_) / 4;
    const int NW = (640 * C_) / 4;
    for (int i = blockIdx.x * blockDim.x + threadIdx.x; i < NX + NW;
         i += gridDim.x * blockDim.x) {
        float4 v;
        __nv_bfloat16* dst;
        if (i < NX) {
            v = ((const float4*)x)[i];
            dst = &g_xb[(size_t)i * 4];
        } else {
            int j = i - NX;
            const int row = (j * 4) / C_;
            const float* src;
            if (row < 64)        src = Wk;
            else if (row < 128)  src = Wv - 64 * C_;
            else                 src = Wq - 128 * C_;
            v = ((const float4*)src)[j];
            dst = &g_Wb[(size_t)j * 4];
        }
        __nv_bfloat162 p0 = __floats2bfloat162_rn(v.x, v.y);
        __nv_bfloat162 p1 = __floats2bfloat162_rn(v.z, v.w);
        ((__nv_bfloat162*)dst)[0] = p0;
        ((__nv_bfloat162*)dst)[1] = p1;
    }
}

// =======================================================================
// Kernel 1: projection GEMM (bf16 HMMA + ldmatrix), 128x128 tiles,
// ring-3, 1 barrier/iter. grid (5 o-tiles of 128, 128 row-tiles of 128).
// ot 0 -> K(64)+V(64); ot 1..4 -> Qt e4m3 (transposed), 128 chans each.
// =======================================================================
#define PITCH 72
#define PAB (128 * PITCH * 2)   // 18432 B per 128-row tile
#define PJ_A 0
#define PJ_B (PJ_A + 3 * PAB)
#define PJ_SMEM_BYTES (PJ_B + 3 * PAB)   // 110592
__global__ __launch_bounds__(256, 2) void proj_hmma(
    const float* __restrict__ bk, const float* __restrict__ bv,
    const float* __restrict__ bq)
{
    extern __shared__ char smc[];
    float* sT = (float*)smc;   // staging [128 oc][132 r] floats

    const uint32_t smu = smem_u32(smc);
    const uint32_t sAu = smu + PJ_A, sBu = smu + PJ_B;

    const int tid = threadIdx.x;
    const int wid = tid >> 5, lane = tid & 31;
    const int g = lane >> 2, t = lane & 3;
    const int wlo = wid & 3;        // row group (32 of 128)
    const int whi = wid >> 2;       // o group (64 of 128)
    const int lrow = lane & 15;
    const int lcol = (lane >> 4) << 3;

    const int ot = blockIdx.x;      // 0..4
    const int row0 = blockIdx.y * 128;
    const int wrow0 = ot * 128;

    #pragma unroll
    for (int pf = 0; pf < 2; pf++) {
        const int kc = pf * 64;
        const uint32_t ab = sAu + pf * PAB, bb = sBu + pf * PAB;
        #pragma unroll
        for (int l = 0; l < 4; l++) {
            int idx = tid + l * 256;
            int r = idx >> 3, ch = idx & 7;
            cp16(ab + r * 144 + ch * 16, &g_xb[(size_t)(row0 + r) * C_ + kc + ch * 8]);
            cp16(bb + r * 144 + ch * 16, &g_Wb[(size_t)(wrow0 + r) * C_ + kc + ch * 8]);
        }
        CP_COMMIT();
    }

    float acc[16][4];
    #pragma unroll
    for (int i = 0; i < 16; i++)
        #pragma unroll
        for (int j = 0; j < 4; j++) acc[i][j] = 0.f;

    const uint32_t aoff0 = ((32 * wlo + lrow) * PITCH + lcol) * 2;
    const uint32_t aoff1 = aoff0 + 16 * PITCH * 2;
    const uint32_t boff0 = ((64 * whi + lrow) * PITCH + lcol) * 2;
    const uint32_t boff1 = boff0 + 16 * PITCH * 2;
    const uint32_t boff2 = boff0 + 32 * PITCH * 2;
    const uint32_t boff3 = boff0 + 48 * PITCH * 2;

    uint32_t sl0 = 0, sl1 = 1, sl2 = 2;
    for (int it = 0; it < 8; it++) {
        CP_WAIT1();
        __syncthreads();

        if (it + 2 < 8) {
            const int kc = (it + 2) * 64;
            const uint32_t ab = sAu + sl2 * PAB, bb = sBu + sl2 * PAB;
            #pragma unroll
            for (int l = 0; l < 4; l++) {
                int idx = tid + l * 256;
                int r = idx >> 3, ch = idx & 7;
                cp16(ab + r * 144 + ch * 16, &g_xb[(size_t)(row0 + r) * C_ + kc + ch * 8]);
                cp16(bb + r * 144 + ch * 16, &g_Wb[(size_t)(wrow0 + r) * C_ + kc + ch * 8]);
            }
        }
        CP_COMMIT();

        const uint32_t Ab = sAu + sl0 * PAB;
        const uint32_t Bb = sBu + sl0 * PAB;

        #pragma unroll
        for (int kk = 0; kk < 64; kk += 16) {
            uint32_t a0[4], a1[4], b0[4], b1[4], b2[4], b3[4];
            ldm4(a0, Ab + aoff0 + kk * 2);
            ldm4(a1, Ab + aoff1 + kk * 2);
            ldm4(b0, Bb + boff0 + kk * 2);
            ldm4(b1, Bb + boff1 + kk * 2);
            ldm4(b2, Bb + boff2 + kk * 2);
            ldm4(b3, Bb + boff3 + kk * 2);
            mma16(acc[0],  a0, b0[0], b0[2]);
            mma16(acc[1],  a0, b0[1], b0[3]);
            mma16(acc[2],  a0, b1[0], b1[2]);
            mma16(acc[3],  a0, b1[1], b1[3]);
            mma16(acc[4],  a0, b2[0], b2[2]);
            mma16(acc[5],  a0, b2[1], b2[3]);
            mma16(acc[6],  a0, b3[0], b3[2]);
            mma16(acc[7],  a0, b3[1], b3[3]);
            mma16(acc[8],  a1, b0[0], b0[2]);
            mma16(acc[9],  a1, b0[1], b0[3]);
            mma16(acc[10], a1, b1[0], b1[2]);
            mma16(acc[11], a1, b1[1], b1[3]);
            mma16(acc[12], a1, b2[0], b2[2]);
            mma16(acc[13], a1, b2[1], b2[3]);
            mma16(acc[14], a1, b3[0], b3[2]);
            mma16(acc[15], a1, b3[1], b3[3]);
        }

        uint32_t tmp = sl0; sl0 = sl1; sl1 = sl2; sl2 = tmp;
    }

    CP_WAIT0();
    __syncthreads();  // sT aliases buffers; all mma done

    #pragma unroll
    for (int jf = 0; jf < 8; jf++) {
        const int oc = 64 * whi + 8 * jf + 2 * t;
        float b0v, b1v;
        if (ot == 0) {
            if (whi == 0) { b0v = __ldg(&bk[oc]);      b1v = __ldg(&bk[oc + 1]); }
            else          { b0v = __ldg(&bv[oc - 64]); b1v = __ldg(&bv[oc - 63]); }
        } else {
            b0v = __ldg(&bq[(ot - 1) * 128 + oc]);
            b1v = __ldg(&bq[(ot - 1) * 128 + oc + 1]);
        }
        #pragma unroll
        for (int fi = 0; fi < 2; fi++) {
            const int r = 32 * wlo + 16 * fi + g;
            const float* d = acc[fi * 8 + jf];
            float v00 = d[0] + b0v;
            float v01 = d[1] + b1v;
            float v10 = d[2] + b0v;
            float v11 = d[3] + b1v;
            if (ot == 0) {
                if (whi == 0) {
                    g_K[(size_t)(row0 + r) * CR_ + oc]         = __float2bfloat16_rn(v00);
                    g_K[(size_t)(row0 + r) * CR_ + oc + 1]     = __float2bfloat16_rn(v01);
                    g_K[(size_t)(row0 + r + 8) * CR_ + oc]     = __float2bfloat16_rn(v10);
                    g_K[(size_t)(row0 + r + 8) * CR_ + oc + 1] = __float2bfloat16_rn(v11);
                } else {
                    const int vc = oc - 64;
                    g_V[(size_t)(row0 + r) * CR_ + vc]         = __float2bfloat16_rn(v00);
                    g_V[(size_t)(row0 + r) * CR_ + vc + 1]     = __float2bfloat16_rn(v01);
                    g_V[(size_t)(row0 + r + 8) * CR_ + vc]     = __float2bfloat16_rn(v10);
                    g_V[(size_t)(row0 + r + 8) * CR_ + vc + 1] = __float2bfloat16_rn(v11);
                }
            } else {
                sT[oc * 132 + r]           = v00;
                sT[(oc + 1) * 132 + r]     = v01;
                sT[oc * 132 + r + 8]       = v10;
                sT[(oc + 1) * 132 + r + 8] = v11;
            }
        }
    }

    if (ot >= 1) {
        __syncthreads();
        const int b  = row0 >> 11;
        const int n0 = row0 & (N_ - 1);
        const size_t qrow0 = (size_t)b * C_ + (ot - 1) * 128;
        #pragma unroll
        for (int l = 0; l < 16; l++) {
            int idx = tid + l * 256;
            int o = idx >> 5, r4 = (idx & 31) << 2;
            float4 v = *(const float4*)&sT[o * 132 + r4];
            uchar4 u;
            u.x = f2e4m3(v.x); u.y = f2e4m3(v.y);
            u.z = f2e4m3(v.z); u.w = f2e4m3(v.w);
            *(uchar4*)&g_Q8[(qrow0 + o) * N_ + n0 + r4] = u;
        }
    }
}

// =======================================================================
// Kernel 2: S = K@V^T (bf16), P = exp(S) -> e4m3, partial den.
// K ring-3, sPT8 x2, copy-out pipelined one iter behind. OCC 3.
// =======================================================================
#define KVB   (64 * PITCH * 2)   // 9216 B
#define P8B   (64 * 80)          // 5120 B
#define PX_SV  0
#define PX_SK  (PX_SV + KVB)            // 3 K slots
#define PX_SPT (PX_SK + 3 * KVB)        // 2 sPT8 buffers
#define PX_DEN (PX_SPT + 2 * P8B)
#define PX_SMEM_BYTES (PX_DEN + 256)    // 47360
__global__ __launch_bounds__(256, 3) void pexp_kernel()
{
    extern __shared__ char smc[];
    float* sDen = (float*)(smc + PX_DEN);

    const uint32_t smu = smem_u32(smc);
    const uint32_t sVu = smu + PX_SV;
    const uint32_t sKu = smu + PX_SK;

    const int tid = threadIdx.x;
    const int wid = tid >> 5, lane = tid & 31;
    const int g = lane >> 2, t = lane & 3;
    const int wlo = wid & 3;
    const int whi = wid >> 2;
    const int lrow = lane & 15;
    const int lcol = (lane >> 4) << 3;

    const int mt = blockIdx.x, nr = blockIdx.y, b = blockIdx.z;
    const int m0 = mt * 64;
    const size_t rb = (size_t)b * N_;
    const size_t pbase = (size_t)b * N_ * N_;

    if (tid < 64) sDen[tid] = 0.f;

    #pragma unroll
    for (int l = 0; l < 2; l++) {
        int idx = tid + l * 256;
        int r = idx >> 3, ch = idx & 7;
        cp16(sVu + r * 144 + ch * 16, &g_V[(rb + m0 + r) * CR_ + ch * 8]);
        cp16(sKu + r * 144 + ch * 16, &g_K[(rb + nr * 512 + r) * CR_ + ch * 8]);
    }
    CP_COMMIT();
    #pragma unroll
    for (int l = 0; l < 2; l++) {
        int idx = tid + l * 256;
        int r = idx >> 3, ch = idx & 7;
        cp16(sKu + KVB + r * 144 + ch * 16, &g_K[(rb + nr * 512 + 64 + r) * CR_ + ch * 8]);
    }
    CP_COMMIT();

    float den[8];
    #pragma unroll
    for (int i = 0; i < 8; i++) den[i] = 0.f;

    uint32_t k0 = 0, k1 = 1, k2 = 2;
    for (int i = 0; i < 8; i++) {
        CP_WAIT1();
        __syncthreads();

        if (i > 0) {
            const unsigned char* spOld =
                (const unsigned char*)(smc + PX_SPT + ((i - 1) & 1) * P8B);
            const int nOld = nr * 512 + (i - 1) * 64;
            int r = tid >> 2, ch = tid & 3;
            float4 v = *(const float4*)(spOld + r * 80 + ch * 16);
            *(float4*)&g_P8[pbase + (size_t)(m0 + r) * N_ + nOld + ch * 16] = v;
        }

        if (i + 2 < 8) {
            const int nn = nr * 512 + (i + 2) * 64;
            const uint32_t kb = sKu + k2 * KVB;
            #pragma unroll
            for (int l = 0; l < 2; l++) {
                int idx = tid + l * 256;
                int r = idx >> 3, ch = idx & 7;
                cp16(kb + r * 144 + ch * 16, &g_K[(rb + nn + r) * CR_ + ch * 8]);
            }
        }
        CP_COMMIT();

        const uint32_t Kb = sKu + k0 * KVB;

        float sacc[4][4];
        #pragma unroll
        for (int ii = 0; ii < 4; ii++)
            #pragma unroll
            for (int j = 0; j < 4; j++) sacc[ii][j] = 0.f;

        #pragma unroll
        for (int kk = 0; kk < 64; kk += 16) {
            uint32_t a[4], bv0[4], bv1[4];
            ldm4(a,   Kb  + ((16 * wlo + lrow) * PITCH + kk + lcol) * 2);
            ldm4(bv0, sVu + ((32 * whi + lrow) * PITCH + kk + lcol) * 2);
            ldm4(bv1, sVu + ((32 * whi + 16 + lrow) * PITCH + kk + lcol) * 2);
            mma16(sacc[0], a, bv0[0], bv0[2]);
            mma16(sacc[1], a, bv0[1], bv0[3]);
            mma16(sacc[2], a, bv1[0], bv1[2]);
            mma16(sacc[3], a, bv1[1], bv1[3]);
        }

        unsigned char* sPT8 = (unsigned char*)(smc + PX_SPT + (i & 1) * P8B);
        const int nloc = 16 * wlo + g;
        #pragma unroll
        for (int jf = 0; jf < 4; jf++) {
            const int mc = 32 * whi + 8 * jf + 2 * t;
            float e00 = __expf(sacc[jf][0]);
            float e01 = __expf(sacc[jf][1]);
            float e10 = __expf(sacc[jf][2]);
            float e11 = __expf(sacc[jf][3]);
            den[2 * jf]     += e00 + e10;
            den[2 * jf + 1] += e01 + e11;
            sPT8[mc * 80 + nloc]           = f2e4m3(e00);
            sPT8[(mc + 1) * 80 + nloc]     = f2e4m3(e01);
            sPT8[mc * 80 + nloc + 8]       = f2e4m3(e10);
            sPT8[(mc + 1) * 80 + nloc + 8] = f2e4m3(e11);
        }

        uint32_t tmp = k0; k0 = k1; k1 = k2; k2 = tmp;
    }

    __syncthreads();
    {
        const unsigned char* spOld = (const unsigned char*)(smc + PX_SPT + P8B);
        const int nOld = nr * 512 + 7 * 64;
        int r = tid >> 2, ch = tid & 3;
        float4 v = *(const float4*)(spOld + r * 80 + ch * 16);
        *(float4*)&g_P8[pbase + (size_t)(m0 + r) * N_ + nOld + ch * 16] = v;
    }

    #pragma unroll
    for (int jf = 0; jf < 4; jf++) {
        const int mc = 32 * whi + 8 * jf + 2 * t;
        atomicAdd(&sDen[mc],     den[2 * jf]);
        atomicAdd(&sDen[mc + 1], den[2 * jf + 1]);
    }
    __syncthreads();
    if (tid < 64)
        g_denp[(size_t)(b * 4 + nr) * N_ + m0 + tid] = sDen[tid];
}

// =======================================================================
// Kernel 3: attn2 — fp8 e4m3 GEMM: Acc[c 128][m 64] = Qt @ P^T.
// grid (4 c-tiles, 32 m-tiles, 8 b) — c fastest for P-tile L2 locality.
// ring-3, occupancy 3 (regs ~80, the measured sweet spot).
// =======================================================================
#define P8PITCH 80
#define PB8 (64  * P8PITCH)
#define QB8 (128 * P8PITCH)
#define A2_P  0
#define A2_Q  (A2_P + 3 * PB8)
#define A2_SMEM_BYTES (A2_Q + 3 * QB8)   // 46080
#define NT2 32
__global__ __launch_bounds__(256, 3) void attn2_kernel(
    const float* __restrict__ x, const float* __restrict__ gamma_p,
    float* __restrict__ out)
{
    extern __shared__ char smc[];
    const uint32_t smu = smem_u32(smc);
    const uint32_t sPu = smu + A2_P;
    const uint32_t sQu = smu + A2_Q;

    const int tid = threadIdx.x;
    const int wid = tid >> 5, lane = tid & 31;
    const int g = lane >> 2, t = lane & 3;
    const int wlo = wid & 3;
    const int whi = wid >> 2;

    const int arow = lane & 15;
    const int acol = (lane >> 4) << 4;
    const int brow = (lane & 7) | ((lane >> 4) << 3);
    const int bcol = ((lane >> 3) & 1) << 4;

    const uint32_t aoff0 = (32 * wlo + arow) * P8PITCH + acol;
    const uint32_t aoff1 = aoff0 + 16 * P8PITCH;
    const uint32_t boff0 = (32 * whi + brow) * P8PITCH + bcol;
    const uint32_t boff1 = boff0 + 16 * P8PITCH;

    const int ct = blockIdx.x, mt = blockIdx.y, b = blockIdx.z;
    const int m0 = mt * 64, c0 = ct * 128;
    const size_t rb = (size_t)b * N_;

    // incremental prefetch pointers (advance 64 B per stage)
    const unsigned char* gP  = &g_P8[(size_t)b * N_ * N_ + (size_t)(m0 + (tid >> 2)) * N_ + (tid & 3) * 16];
    const unsigned char* gQ0 = &g_Q8[((size_t)b * C_ + c0 + (tid >> 2)) * N_ + (tid & 3) * 16];
    const unsigned char* gQ1 = gQ0 + (size_t)64 * N_;
    const uint32_t pdst  = sPu + (tid >> 2) * P8PITCH + (tid & 3) * 16;
    const uint32_t qdst0 = sQu + (tid >> 2) * P8PITCH + (tid & 3) * 16;
    const uint32_t qdst1 = qdst0 + 64 * P8PITCH;

    // prologue: stages 0,1
    #pragma unroll
    for (int s = 0; s < 2; s++) {
        cp16(pdst  + s * PB8, gP  + s * 64);
        cp16(qdst0 + s * QB8, gQ0 + s * 64);
        cp16(qdst1 + s * QB8, gQ1 + s * 64);
        CP_COMMIT();
    }
    gP += 128; gQ0 += 128; gQ1 += 128;

    float acc[8][4];
    #pragma unroll
    for (int i = 0; i < 8; i++)
        #pragma unroll
        for (int j = 0; j < 4; j++) acc[i][j] = 0.f;

    uint32_t sl0 = 0, sl1 = 1, sl2 = 2;
    for (int nt = 0; nt < NT2; nt++) {
        CP_WAIT1();
        __syncthreads();

        if (nt + 2 < NT2) {
            cp16(pdst  + sl2 * PB8, gP);
            cp16(qdst0 + sl2 * QB8, gQ0);
            cp16(qdst1 + sl2 * QB8, gQ1);
            gP += 64; gQ0 += 64; gQ1 += 64;
        }
        CP_COMMIT();

        const uint32_t Pb = sPu + sl0 * PB8;
        const uint32_t Qb = sQu + sl0 * QB8;

        #pragma unroll
        for (int kk = 0; kk < 64; kk += 32) {
            uint32_t a0[4], a1[4], p0[4], p1[4];
            ldm4(a0, Qb + aoff0 + kk);
            ldm4(a1, Qb + aoff1 + kk);
            ldm4(p0, Pb + boff0 + kk);
            ldm4(p1, Pb + boff1 + kk);
            mma32(acc[0], a0, p0[0], p0[1]);
            mma32(acc[1], a0, p0[2], p0[3]);
            mma32(acc[2], a0, p1[0], p1[1]);
            mma32(acc[3], a0, p1[2], p1[3]);
            mma32(acc[4], a1, p0[0], p0[1]);
            mma32(acc[5], a1, p0[2], p0[3]);
            mma32(acc[6], a1, p1[0], p1[1]);
            mma32(acc[7], a1, p1[2], p1[3]);
        }

        uint32_t tmp = sl0; sl0 = sl1; sl1 = sl2; sl2 = tmp;
    }

    // ---- epilogue ----
    const float gam = gamma_p[0];
    #pragma unroll
    for (int mj = 0; mj < 4; mj++) {
        const int mc = 32 * whi + 8 * mj + 2 * t;
        float d0 = 0.f, d1 = 0.f;
        #pragma unroll
        for (int nr = 0; nr < 4; nr++) {
            d0 += __ldg(&g_denp[(size_t)(b * 4 + nr) * N_ + m0 + mc]);
            d1 += __ldg(&g_denp[(size_t)(b * 4 + nr) * N_ + m0 + mc + 1]);
        }
        const float di0 = gam / d0;
        const float di1 = gam / d1;
        #pragma unroll
        for (int fi = 0; fi < 2; fi++) {
            const int cc = c0 + 32 * wlo + 16 * fi + g;
            const size_t r0a = (rb + m0 + mc) * C_ + cc;
            const size_t r1a = (rb + m0 + mc + 1) * C_ + cc;
            const float* d = acc[fi * 4 + mj];
            out[r0a]     = d[0] * di0 + __ldg(&x[r0a]);
            out[r1a]     = d[1] * di1 + __ldg(&x[r1a]);
            out[r0a + 8] = d[2] * di0 + __ldg(&x[r0a + 8]);
            out[r1a + 8] = d[3] * di1 + __ldg(&x[r1a + 8]);
        }
    }
}

// =======================================================================
extern "C" void kernel_launch(void* const* d_in, const int* in_sizes, int n_in,
                              void* d_out, int out_size)
{
    const float* x     = (const float*)d_in[0];
    const float* Wk    = (const float*)d_in[1];
    const float* bk    = (const float*)d_in[2];
    const float* Wv    = (const float*)d_in[3];
    const float* bv    = (const float*)d_in[4];
    const float* Wq    = (const float*)d_in[5];
    const float* bq    = (const float*)d_in[6];
    const float* gamma = (const float*)d_in[7];
    float* out = (float*)d_out;

    cudaFuncSetAttribute(proj_hmma,    cudaFuncAttributeMaxDynamicSharedMemorySize, PJ_SMEM_BYTES);
    cudaFuncSetAttribute(pexp_kernel,  cudaFuncAttributeMaxDynamicSharedMemorySize, PX_SMEM_BYTES);
    cudaFuncSetAttribute(attn2_kernel, cudaFuncAttributeMaxDynamicSharedMemorySize, A2_SMEM_BYTES);

    cvt_kernel<<<1184, 256>>>(x, Wk, Wv, Wq);
    proj_hmma<<<dim3(5, 128), 256, PJ_SMEM_BYTES>>>(bk, bv, bq);
    pexp_kernel<<<dim3(32, 4, B_), 256, PX_SMEM_BYTES>>>();
    attn2_kernel<<<dim3(4, 32, B_), 256, A2_SMEM_BYTES>>>(x, gamma, out);
}

// round 17
// speedup vs baseline: 2.2555x; 1.0192x over previous
#include <cuda_runtime.h>
#include <cuda_bf16.h>
#include <cuda_fp8.h>
#include <cstdint>

#define B_  8
#define N_  2048
#define C_  512
#define CR_ 64

// Device-global scratch (no allocs allowed).
__device__ __nv_bfloat16 g_xb[(size_t)B_ * N_ * C_];    // x in bf16
__device__ __nv_bfloat16 g_Wb[(size_t)640 * C_];        // [Wk;Wv;Wq] bf16
__device__ __nv_bfloat16 g_K [(size_t)B_ * N_ * CR_];   // [b*N+n][64]
__device__ __nv_bfloat16 g_V [(size_t)B_ * N_ * CR_];   // [b*N+m][64]
__device__ unsigned char g_Q8[(size_t)B_ * C_ * N_];    // Qt e4m3: [b*C+c][n]
__device__ unsigned char g_P8[(size_t)B_ * N_ * N_];    // P^T e4m3: [b][m][n]
__device__ float         g_denp[(size_t)B_ * 4 * N_];   // partial den

__device__ __forceinline__ uint32_t smem_u32(const void* p) {
    uint32_t a;
    asm("{ .reg .u64 t; cvta.to.shared.u64 t, %1; cvt.u32.u64 %0, t; }" : "=r"(a) : "l"(p));
    return a;
}
__device__ __forceinline__ void cp16(uint32_t dst, const void* src) {
    asm volatile("cp.async.cg.shared.global [%0], [%1], 16;" :: "r"(dst), "l"(src));
}
#define CP_COMMIT() asm volatile("cp.async.commit_group;" ::: "memory")
#define CP_WAIT0()  asm volatile("cp.async.wait_group 0;"  ::: "memory")
#define CP_WAIT1()  asm volatile("cp.async.wait_group 1;"  ::: "memory")

__device__ __forceinline__ unsigned char f2e4m3(float f) {
    return (unsigned char)__nv_cvt_float_to_fp8(f, __NV_SATFINITE, __NV_E4M3);
}

// bf16 warp mma: D(16x8) += A(16x16)*B(16x8)
__device__ __forceinline__ void mma16(float d[4], const uint32_t a[4], uint32_t b0, uint32_t b1) {
    asm volatile(
        "mma.sync.aligned.m16n8k16.row.col.f32.bf16.bf16.f32 "
        "{%0,%1,%2,%3}, {%4,%5,%6,%7}, {%8,%9}, {%0,%1,%2,%3};"
        : "+f"(d[0]), "+f"(d[1]), "+f"(d[2]), "+f"(d[3])
        : "r"(a[0]), "r"(a[1]), "r"(a[2]), "r"(a[3]), "r"(b0), "r"(b1));
}
// fp8 warp mma: D(16x8) += A(16x32)*B(32x8), e4m3
__device__ __forceinline__ void mma32(float d[4], const uint32_t a[4], uint32_t b0, uint32_t b1) {
    asm volatile(
        "mma.sync.aligned.m16n8k32.row.col.f32.e4m3.e4m3.f32 "
        "{%0,%1,%2,%3}, {%4,%5,%6,%7}, {%8,%9}, {%0,%1,%2,%3};"
        : "+f"(d[0]), "+f"(d[1]), "+f"(d[2]), "+f"(d[3])
        : "r"(a[0]), "r"(a[1]), "r"(a[2]), "r"(a[3]), "r"(b0), "r"(b1));
}
__device__ __forceinline__ void ldm4(uint32_t r[4], uint32_t addr) {
    asm volatile("ldmatrix.sync.aligned.m8n8.x4.shared.b16 {%0,%1,%2,%3}, [%4];"
        : "=r"(r[0]), "=r"(r[1]), "=r"(r[2]), "=r"(r[3]) : "r"(addr));
}

// =======================================================================
// Kernel 0: fp32 -> bf16 conversion of x and [Wk;Wv;Wq].
// =======================================================================
__global__ __launch_bounds__(256) void cvt_kernel(
    const float* __restrict__ x,
    const float* __restrict__ Wk, const float* __restrict__ Wv,
    const float* __restrict__ Wq)
{
    const int NX = (B_ * N_ * C_) / 4;
    const int NW = (640 * C_) / 4;
    for (int i = blockIdx.x * blockDim.x + threadIdx.x; i < NX + NW;
         i += gridDim.x * blockDim.x) {
        float4 v;
        __nv_bfloat16* dst;
        if (i < NX) {
            v = ((const float4*)x)[i];
            dst = &g_xb[(size_t)i * 4];
        } else {
            int j = i - NX;
            const int row = (j * 4) / C_;
            const float* src;
            if (row < 64)        src = Wk;
            else if (row < 128)  src = Wv - 64 * C_;
            else                 src = Wq - 128 * C_;
            v = ((const float4*)src)[j];
            dst = &g_Wb[(size_t)j * 4];
        }
        __nv_bfloat162 p0 = __floats2bfloat162_rn(v.x, v.y);
        __nv_bfloat162 p1 = __floats2bfloat162_rn(v.z, v.w);
        ((__nv_bfloat162*)dst)[0] = p0;
        ((__nv_bfloat162*)dst)[1] = p1;
    }
}

// =======================================================================
// Kernel 1: projection GEMM (bf16 HMMA + ldmatrix), 128x64 tiles,
// ring-2, occupancy 3. grid (10 o-tiles of 64, 128 row-tiles of 128).
// ot0->K, ot1->V, ot2..9 -> Q8 e4m3 (transposed), 64 chans each.
// =======================================================================
#define PITCH 72
#define PAB (128 * PITCH * 2)   // 18432 B (x rows)
#define PBB (64  * PITCH * 2)   //  9216 B (W rows)
#define PJ_A 0
#define PJ_B (PJ_A + 2 * PAB)
#define PJ_SMEM_BYTES (PJ_B + 2 * PBB)   // 55296 -> 3 CTAs/SM
__global__ __launch_bounds__(256, 3) void proj_hmma(
    const float* __restrict__ bk, const float* __restrict__ bv,
    const float* __restrict__ bq)
{
    extern __shared__ char smc[];
    float* sT = (float*)smc;   // staging [64 oc][132 r] floats = 33792 B

    const uint32_t smu = smem_u32(smc);
    const uint32_t sAu = smu + PJ_A, sBu = smu + PJ_B;

    const int tid = threadIdx.x;
    const int wid = tid >> 5, lane = tid & 31;
    const int g = lane >> 2, t = lane & 3;
    const int wlo = wid & 3;        // row group (32 of 128)
    const int whi = wid >> 2;       // o group (32 of 64)
    const int lrow = lane & 15;
    const int lcol = (lane >> 4) << 3;

    const int ot = blockIdx.x;      // 0..9
    const int row0 = blockIdx.y * 128;
    const int wrow0 = ot * 64;      // row offset in g_Wb

    const float* bias;
    if (ot == 0)      bias = bk;
    else if (ot == 1) bias = bv;
    else              bias = bq + (ot - 2) * 64;

    // prologue: stages 0,1
    #pragma unroll
    for (int pf = 0; pf < 2; pf++) {
        const int kc = pf * 64;
        const uint32_t ab = sAu + pf * PAB, bb = sBu + pf * PBB;
        #pragma unroll
        for (int l = 0; l < 4; l++) {
            int idx = tid + l * 256;
            int r = idx >> 3, ch = idx & 7;
            cp16(ab + r * 144 + ch * 16, &g_xb[(size_t)(row0 + r) * C_ + kc + ch * 8]);
        }
        #pragma unroll
        for (int l = 0; l < 2; l++) {
            int idx = tid + l * 256;
            int r = idx >> 3, ch = idx & 7;
            cp16(bb + r * 144 + ch * 16, &g_Wb[(size_t)(wrow0 + r) * C_ + kc + ch * 8]);
        }
        CP_COMMIT();
    }

    float acc[8][4];   // [fi*4+jf]
    #pragma unroll
    for (int i = 0; i < 8; i++)
        #pragma unroll
        for (int j = 0; j < 4; j++) acc[i][j] = 0.f;

    const uint32_t aoff0 = ((32 * wlo + lrow) * PITCH + lcol) * 2;
    const uint32_t aoff1 = aoff0 + 16 * PITCH * 2;
    const uint32_t boff0 = ((32 * whi + lrow) * PITCH + lcol) * 2;
    const uint32_t boff1 = boff0 + 16 * PITCH * 2;

    for (int it = 0; it < 8; it++) {
        CP_WAIT1();
        __syncthreads();

        const uint32_t Ab = sAu + (it & 1) * PAB;
        const uint32_t Bb = sBu + (it & 1) * PBB;

        #pragma unroll
        for (int kk = 0; kk < 64; kk += 16) {
            uint32_t a0[4], a1[4], b0[4], b1[4];
            ldm4(a0, Ab + aoff0 + kk * 2);
            ldm4(a1, Ab + aoff1 + kk * 2);
            ldm4(b0, Bb + boff0 + kk * 2);
            ldm4(b1, Bb + boff1 + kk * 2);
            mma16(acc[0], a0, b0[0], b0[2]);
            mma16(acc[1], a0, b0[1], b0[3]);
            mma16(acc[2], a0, b1[0], b1[2]);
            mma16(acc[3], a0, b1[1], b1[3]);
            mma16(acc[4], a1, b0[0], b0[2]);
            mma16(acc[5], a1, b0[1], b0[3]);
            mma16(acc[6], a1, b1[0], b1[2]);
            mma16(acc[7], a1, b1[1], b1[3]);
        }
        __syncthreads();   // buffer (it&1) free

        if (it + 2 < 8) {
            const int kc = (it + 2) * 64;
            const uint32_t ab = sAu + (it & 1) * PAB, bb = sBu + (it & 1) * PBB;
            #pragma unroll
            for (int l = 0; l < 4; l++) {
                int idx = tid + l * 256;
                int r = idx >> 3, ch = idx & 7;
                cp16(ab + r * 144 + ch * 16, &g_xb[(size_t)(row0 + r) * C_ + kc + ch * 8]);
            }
            #pragma unroll
            for (int l = 0; l < 2; l++) {
                int idx = tid + l * 256;
                int r = idx >> 3, ch = idx & 7;
                cp16(bb + r * 144 + ch * 16, &g_Wb[(size_t)(wrow0 + r) * C_ + kc + ch * 8]);
            }
        }
        CP_COMMIT();
    }

    CP_WAIT0();
    __syncthreads();  // sT aliases A buffers

    #pragma unroll
    for (int jf = 0; jf < 4; jf++) {
        const int oc = 32 * whi + 8 * jf + 2 * t;
        const float b0v = __ldg(&bias[oc]);
        const float b1v = __ldg(&bias[oc + 1]);
        #pragma unroll
        for (int fi = 0; fi < 2; fi++) {
            const int r = 32 * wlo + 16 * fi + g;
            const float* d = acc[4 * fi + jf];
            float v00 = d[0] + b0v;
            float v01 = d[1] + b1v;
            float v10 = d[2] + b0v;
            float v11 = d[3] + b1v;
            if (ot == 0) {
                g_K[(size_t)(row0 + r) * CR_ + oc]         = __float2bfloat16_rn(v00);
                g_K[(size_t)(row0 + r) * CR_ + oc + 1]     = __float2bfloat16_rn(v01);
                g_K[(size_t)(row0 + r + 8) * CR_ + oc]     = __float2bfloat16_rn(v10);
                g_K[(size_t)(row0 + r + 8) * CR_ + oc + 1] = __float2bfloat16_rn(v11);
            } else if (ot == 1) {
                g_V[(size_t)(row0 + r) * CR_ + oc]         = __float2bfloat16_rn(v00);
                g_V[(size_t)(row0 + r) * CR_ + oc + 1]     = __float2bfloat16_rn(v01);
                g_V[(size_t)(row0 + r + 8) * CR_ + oc]     = __float2bfloat16_rn(v10);
                g_V[(size_t)(row0 + r + 8) * CR_ + oc + 1] = __float2bfloat16_rn(v11);
            } else {
                sT[oc * 132 + r]           = v00;
                sT[(oc + 1) * 132 + r]     = v01;
                sT[oc * 132 + r + 8]       = v10;
                sT[(oc + 1) * 132 + r + 8] = v11;
            }
        }
    }

    if (ot >= 2) {
        __syncthreads();
        const int b  = row0 >> 11;
        const int n0 = row0 & (N_ - 1);
        const size_t qrow0 = (size_t)b * C_ + (ot - 2) * 64;
        #pragma unroll
        for (int l = 0; l < 8; l++) {
            int idx = tid + l * 256;            // 0..2047 = 64 o x 32 r-quads
            int o = idx >> 5, r4 = (idx & 31) << 2;
            float4 v = *(const float4*)&sT[o * 132 + r4];
            uchar4 u;
            u.x = f2e4m3(v.x); u.y = f2e4m3(v.y);
            u.z = f2e4m3(v.z); u.w = f2e4m3(v.w);
            *(uchar4*)&g_Q8[(qrow0 + o) * N_ + n0 + r4] = u;
        }
    }
}

// =======================================================================
// Kernel 2: S = K@V^T (bf16), P = exp(S) -> e4m3, partial den.
// K ring-3, sPT8 x2, copy-out pipelined one iter behind. OCC 3.
// =======================================================================
#define KVB   (64 * PITCH * 2)   // 9216 B
#define P8B   (64 * 80)          // 5120 B
#define PX_SV  0
#define PX_SK  (PX_SV + KVB)            // 3 K slots
#define PX_SPT (PX_SK + 3 * KVB)        // 2 sPT8 buffers
#define PX_DEN (PX_SPT + 2 * P8B)
#define PX_SMEM_BYTES (PX_DEN + 256)    // 47360
__global__ __launch_bounds__(256, 3) void pexp_kernel()
{
    extern __shared__ char smc[];
    float* sDen = (float*)(smc + PX_DEN);

    const uint32_t smu = smem_u32(smc);
    const uint32_t sVu = smu + PX_SV;
    const uint32_t sKu = smu + PX_SK;

    const int tid = threadIdx.x;
    const int wid = tid >> 5, lane = tid & 31;
    const int g = lane >> 2, t = lane & 3;
    const int wlo = wid & 3;
    const int whi = wid >> 2;
    const int lrow = lane & 15;
    const int lcol = (lane >> 4) << 3;

    const int mt = blockIdx.x, nr = blockIdx.y, b = blockIdx.z;
    const int m0 = mt * 64;
    const size_t rb = (size_t)b * N_;
    const size_t pbase = (size_t)b * N_ * N_;

    if (tid < 64) sDen[tid] = 0.f;

    #pragma unroll
    for (int l = 0; l < 2; l++) {
        int idx = tid + l * 256;
        int r = idx >> 3, ch = idx & 7;
        cp16(sVu + r * 144 + ch * 16, &g_V[(rb + m0 + r) * CR_ + ch * 8]);
        cp16(sKu + r * 144 + ch * 16, &g_K[(rb + nr * 512 + r) * CR_ + ch * 8]);
    }
    CP_COMMIT();
    #pragma unroll
    for (int l = 0; l < 2; l++) {
        int idx = tid + l * 256;
        int r = idx >> 3, ch = idx & 7;
        cp16(sKu + KVB + r * 144 + ch * 16, &g_K[(rb + nr * 512 + 64 + r) * CR_ + ch * 8]);
    }
    CP_COMMIT();

    float den[8];
    #pragma unroll
    for (int i = 0; i < 8; i++) den[i] = 0.f;

    uint32_t k0 = 0, k1 = 1, k2 = 2;
    for (int i = 0; i < 8; i++) {
        CP_WAIT1();
        __syncthreads();

        if (i > 0) {
            const unsigned char* spOld =
                (const unsigned char*)(smc + PX_SPT + ((i - 1) & 1) * P8B);
            const int nOld = nr * 512 + (i - 1) * 64;
            int r = tid >> 2, ch = tid & 3;
            float4 v = *(const float4*)(spOld + r * 80 + ch * 16);
            *(float4*)&g_P8[pbase + (size_t)(m0 + r) * N_ + nOld + ch * 16] = v;
        }

        if (i + 2 < 8) {
            const int nn = nr * 512 + (i + 2) * 64;
            const uint32_t kb = sKu + k2 * KVB;
            #pragma unroll
            for (int l = 0; l < 2; l++) {
                int idx = tid + l * 256;
                int r = idx >> 3, ch = idx & 7;
                cp16(kb + r * 144 + ch * 16, &g_K[(rb + nn + r) * CR_ + ch * 8]);
            }
        }
        CP_COMMIT();

        const uint32_t Kb = sKu + k0 * KVB;

        float sacc[4][4];
        #pragma unroll
        for (int ii = 0; ii < 4; ii++)
            #pragma unroll
            for (int j = 0; j < 4; j++) sacc[ii][j] = 0.f;

        #pragma unroll
        for (int kk = 0; kk < 64; kk += 16) {
            uint32_t a[4], bv0[4], bv1[4];
            ldm4(a,   Kb  + ((16 * wlo + lrow) * PITCH + kk + lcol) * 2);
            ldm4(bv0, sVu + ((32 * whi + lrow) * PITCH + kk + lcol) * 2);
            ldm4(bv1, sVu + ((32 * whi + 16 + lrow) * PITCH + kk + lcol) * 2);
            mma16(sacc[0], a, bv0[0], bv0[2]);
            mma16(sacc[1], a, bv0[1], bv0[3]);
            mma16(sacc[2], a, bv1[0], bv1[2]);
            mma16(sacc[3], a, bv1[1], bv1[3]);
        }

        unsigned char* sPT8 = (unsigned char*)(smc + PX_SPT + (i & 1) * P8B);
        const int nloc = 16 * wlo + g;
        #pragma unroll
        for (int jf = 0; jf < 4; jf++) {
            const int mc = 32 * whi + 8 * jf + 2 * t;
            float e00 = __expf(sacc[jf][0]);
            float e01 = __expf(sacc[jf][1]);
            float e10 = __expf(sacc[jf][2]);
            float e11 = __expf(sacc[jf][3]);
            den[2 * jf]     += e00 + e10;
            den[2 * jf + 1] += e01 + e11;
            sPT8[mc * 80 + nloc]           = f2e4m3(e00);
            sPT8[(mc + 1) * 80 + nloc]     = f2e4m3(e01);
            sPT8[mc * 80 + nloc + 8]       = f2e4m3(e10);
            sPT8[(mc + 1) * 80 + nloc + 8] = f2e4m3(e11);
        }

        uint32_t tmp = k0; k0 = k1; k1 = k2; k2 = tmp;
    }

    __syncthreads();
    {
        const unsigned char* spOld = (const unsigned char*)(smc + PX_SPT + P8B);
        const int nOld = nr * 512 + 7 * 64;
        int r = tid >> 2, ch = tid & 3;
        float4 v = *(const float4*)(spOld + r * 80 + ch * 16);
        *(float4*)&g_P8[pbase + (size_t)(m0 + r) * N_ + nOld + ch * 16] = v;
    }

    #pragma unroll
    for (int jf = 0; jf < 4; jf++) {
        const int mc = 32 * whi + 8 * jf + 2 * t;
        atomicAdd(&sDen[mc],     den[2 * jf]);
        atomicAdd(&sDen[mc + 1], den[2 * jf + 1]);
    }
    __syncthreads();
    if (tid < 64)
        g_denp[(size_t)(b * 4 + nr) * N_ + m0 + tid] = sDen[tid];
}

// =======================================================================
// Kernel 3: attn2 — fp8 e4m3 GEMM: Acc[c 128][m 64] = Qt @ P^T.
// grid (4 c-tiles, 32 m-tiles, 8 b) — c fastest for P-tile L2 locality.
// ring-3, occupancy 3 (regs ~80, the measured sweet spot).
// =======================================================================
#define P8PITCH 80
#define PB8 (64  * P8PITCH)
#define QB8 (128 * P8PITCH)
#define A2_P  0
#define A2_Q  (A2_P + 3 * PB8)
#define A2_SMEM_BYTES (A2_Q + 3 * QB8)   // 46080
#define NT2 32
__global__ __launch_bounds__(256, 3) void attn2_kernel(
    const float* __restrict__ x, const float* __restrict__ gamma_p,
    float* __restrict__ out)
{
    extern __shared__ char smc[];
    const uint32_t smu = smem_u32(smc);
    const uint32_t sPu = smu + A2_P;
    const uint32_t sQu = smu + A2_Q;

    const int tid = threadIdx.x;
    const int wid = tid >> 5, lane = tid & 31;
    const int g = lane >> 2, t = lane & 3;
    const int wlo = wid & 3;
    const int whi = wid >> 2;

    const int arow = lane & 15;
    const int acol = (lane >> 4) << 4;
    const int brow = (lane & 7) | ((lane >> 4) << 3);
    const int bcol = ((lane >> 3) & 1) << 4;

    const uint32_t aoff0 = (32 * wlo + arow) * P8PITCH + acol;
    const uint32_t aoff1 = aoff0 + 16 * P8PITCH;
    const uint32_t boff0 = (32 * whi + brow) * P8PITCH + bcol;
    const uint32_t boff1 = boff0 + 16 * P8PITCH;

    const int ct = blockIdx.x, mt = blockIdx.y, b = blockIdx.z;
    const int m0 = mt * 64, c0 = ct * 128;
    const size_t rb = (size_t)b * N_;

    // incremental prefetch pointers (advance 64 B per stage)
    const unsigned char* gP  = &g_P8[(size_t)b * N_ * N_ + (size_t)(m0 + (tid >> 2)) * N_ + (tid & 3) * 16];
    const unsigned char* gQ0 = &g_Q8[((size_t)b * C_ + c0 + (tid >> 2)) * N_ + (tid & 3) * 16];
    const unsigned char* gQ1 = gQ0 + (size_t)64 * N_;
    const uint32_t pdst  = sPu + (tid >> 2) * P8PITCH + (tid & 3) * 16;
    const uint32_t qdst0 = sQu + (tid >> 2) * P8PITCH + (tid & 3) * 16;
    const uint32_t qdst1 = qdst0 + 64 * P8PITCH;

    // prologue: stages 0,1
    #pragma unroll
    for (int s = 0; s < 2; s++) {
        cp16(pdst  + s * PB8, gP  + s * 64);
        cp16(qdst0 + s * QB8, gQ0 + s * 64);
        cp16(qdst1 + s * QB8, gQ1 + s * 64);
        CP_COMMIT();
    }
    gP += 128; gQ0 += 128; gQ1 += 128;

    float acc[8][4];
    #pragma unroll
    for (int i = 0; i < 8; i++)
        #pragma unroll
        for (int j = 0; j < 4; j++) acc[i][j] = 0.f;

    uint32_t sl0 = 0, sl1 = 1, sl2 = 2;
    for (int nt = 0; nt < NT2; nt++) {
        CP_WAIT1();
        __syncthreads();

        if (nt + 2 < NT2) {
            cp16(pdst  + sl2 * PB8, gP);
            cp16(qdst0 + sl2 * QB8, gQ0);
            cp16(qdst1 + sl2 * QB8, gQ1);
            gP += 64; gQ0 += 64; gQ1 += 64;
        }
        CP_COMMIT();

        const uint32_t Pb = sPu + sl0 * PB8;
        const uint32_t Qb = sQu + sl0 * QB8;

        #pragma unroll
        for (int kk = 0; kk < 64; kk += 32) {
            uint32_t a0[4], a1[4], p0[4], p1[4];
            ldm4(a0, Qb + aoff0 + kk);
            ldm4(a1, Qb + aoff1 + kk);
            ldm4(p0, Pb + boff0 + kk);
            ldm4(p1, Pb + boff1 + kk);
            mma32(acc[0], a0, p0[0], p0[1]);
            mma32(acc[1], a0, p0[2], p0[3]);
            mma32(acc[2], a0, p1[0], p1[1]);
            mma32(acc[3], a0, p1[2], p1[3]);
            mma32(acc[4], a1, p0[0], p0[1]);
            mma32(acc[5], a1, p0[2], p0[3]);
            mma32(acc[6], a1, p1[0], p1[1]);
            mma32(acc[7], a1, p1[2], p1[3]);
        }

        uint32_t tmp = sl0; sl0 = sl1; sl1 = sl2; sl2 = tmp;
    }

    // ---- epilogue ----
    const float gam = gamma_p[0];
    #pragma unroll
    for (int mj = 0; mj < 4; mj++) {
        const int mc = 32 * whi + 8 * mj + 2 * t;
        float d0 = 0.f, d1 = 0.f;
        #pragma unroll
        for (int nr = 0; nr < 4; nr++) {
            d0 += __ldg(&g_denp[(size_t)(b * 4 + nr) * N_ + m0 + mc]);
            d1 += __ldg(&g_denp[(size_t)(b * 4 + nr) * N_ + m0 + mc + 1]);
        }
        const float di0 = gam / d0;
        const float di1 = gam / d1;
        #pragma unroll
        for (int fi = 0; fi < 2; fi++) {
            const int cc = c0 + 32 * wlo + 16 * fi + g;
            const size_t r0a = (rb + m0 + mc) * C_ + cc;
            const size_t r1a = (rb + m0 + mc + 1) * C_ + cc;
            const float* d = acc[fi * 4 + mj];
            out[r0a]     = d[0] * di0 + __ldg(&x[r0a]);
            out[r1a]     = d[1] * di1 + __ldg(&x[r1a]);
            out[r0a + 8] = d[2] * di0 + __ldg(&x[r0a + 8]);
            out[r1a + 8] = d[3] * di1 + __ldg(&x[r1a + 8]);
        }
    }
}

// =======================================================================
extern "C" void kernel_launch(void* const* d_in, const int* in_sizes, int n_in,
                              void* d_out, int out_size)
{
    const float* x     = (const float*)d_in[0];
    const float* Wk    = (const float*)d_in[1];
    const float* bk    = (const float*)d_in[2];
    const float* Wv    = (const float*)d_in[3];
    const float* bv    = (const float*)d_in[4];
    const float* Wq    = (const float*)d_in[5];
    const float* bq    = (const float*)d_in[6];
    const float* gamma = (const float*)d_in[7];
    float* out = (float*)d_out;

    cudaFuncSetAttribute(proj_hmma,    cudaFuncAttributeMaxDynamicSharedMemorySize, PJ_SMEM_BYTES);
    cudaFuncSetAttribute(pexp_kernel,  cudaFuncAttributeMaxDynamicSharedMemorySize, PX_SMEM_BYTES);
    cudaFuncSetAttribute(attn2_kernel, cudaFuncAttributeMaxDynamicSharedMemorySize, A2_SMEM_BYTES);

    cvt_kernel<<<1184, 256>>>(x, Wk, Wv, Wq);
    proj_hmma<<<dim3(10, 128), 256, PJ_SMEM_BYTES>>>(bk, bv, bq);
    pexp_kernel<<<dim3(32, 4, B_), 256, PX_SMEM_BYTES>>>();
    attn2_kernel<<<dim3(4, 32, B_), 256, A2_SMEM_BYTES>>>(x, gamma, out);
}